// round 12
// baseline (speedup 1.0000x reference)
#include <cuda_runtime.h>
#include <cuda_bf16.h>
#include <math.h>

#define B 8
#define DIM 8192
#define HEAD_DIM 128
#define N_KV 8
#define N_REP 8
#define NH 64
#define KV 4096
#define E 8
#define FD 2048
#define FE 1024
#define QKV_N 10240
#define SPLITS 16
#define JSPL (KV / SPLITS)   /* 256 */
#define JWARP (JSPL / 8)     /* 32  */

// ---------------- scratch ----------------
__device__ float g_an[B * DIM];
__device__ float g_qkv[B * QKV_N];
__device__ float g_q[B * NH * HEAD_DIM];
__device__ float g_knew[B * N_KV * HEAD_DIM];
__device__ float g_vnew[B * N_KV * HEAD_DIM];
__device__ float g_attn[B * DIM];
__device__ float g_h[B * DIM];
__device__ float g_fin[B * DIM];
__device__ float g_t1[B * FD];
__device__ float g_t3[B * FD];
__device__ float g_g[B * FD];
__device__ float g_glog[B * E];
__device__ float g_wexp[B * E];
__device__ float g_h1[B * E * FE];
__device__ float g_h3[B * E * FE];
__device__ float g_ge[B * E * FE];
__device__ float g_part_o[(size_t)B * N_KV * SPLITS * N_REP * HEAD_DIM];
__device__ float g_part_m[B * N_KV * SPLITS * N_REP];
__device__ float g_part_l[B * N_KV * SPLITS * N_REP];

// ---------------- rmsnorm ----------------
__global__ void rmsnorm_kernel(const float* __restrict__ x, const float* __restrict__ w,
                               float* __restrict__ out) {
    int b = blockIdx.x;
    const float* xb = x + (size_t)b * DIM;
    float* ob = out + (size_t)b * DIM;
    float ss = 0.f;
    for (int i = threadIdx.x; i < DIM; i += blockDim.x) {
        float v = xb[i];
        ss += v * v;
    }
    __shared__ float red[32];
    for (int off = 16; off > 0; off >>= 1) ss += __shfl_xor_sync(0xffffffffu, ss, off);
    int lane = threadIdx.x & 31, warp = threadIdx.x >> 5;
    if (lane == 0) red[warp] = ss;
    __syncthreads();
    if (warp == 0) {
        float v = (lane < (int)(blockDim.x >> 5)) ? red[lane] : 0.f;
        for (int off = 16; off > 0; off >>= 1) v += __shfl_xor_sync(0xffffffffu, v, off);
        if (lane == 0) red[0] = v;
    }
    __syncthreads();
    float scale = rsqrtf(red[0] / (float)DIM + 1e-5f);
    for (int i = threadIdx.x; i < DIM; i += blockDim.x)
        ob[i] = xb[i] * scale * w[i];
}

// ---------------- column-major GEMV (x[B,K] @ W[K,N]), k-split + atomics ----------------
__global__ void __launch_bounds__(128, 4)
gemv_cm4_kernel(const float* __restrict__ x, const float* __restrict__ W,
                float* __restrict__ out, int K, int N, int kchunk) {
    int n4 = blockIdx.x * blockDim.x + threadIdx.x;
    int N4 = N >> 2;
    int k0 = blockIdx.y * kchunk;
    __shared__ float xs[B][128];
    float acc[4][B];
#pragma unroll
    for (int r = 0; r < 4; ++r)
#pragma unroll
        for (int b = 0; b < B; ++b) acc[r][b] = 0.f;
    const float4* W4 = (const float4*)W;
    for (int kb = k0; kb < k0 + kchunk; kb += 128) {
        __syncthreads();
        for (int i = threadIdx.x; i < B * 128; i += blockDim.x)
            xs[i >> 7][i & 127] = x[(size_t)(i >> 7) * K + kb + (i & 127)];
        __syncthreads();
#pragma unroll 8
        for (int kk = 0; kk < 128; ++kk) {
            float4 w = W4[(size_t)(kb + kk) * N4 + n4];
#pragma unroll
            for (int b = 0; b < B; ++b) {
                float xv = xs[b][kk];
                acc[0][b] += w.x * xv;
                acc[1][b] += w.y * xv;
                acc[2][b] += w.z * xv;
                acc[3][b] += w.w * xv;
            }
        }
    }
    int n = n4 * 4;
#pragma unroll
    for (int b = 0; b < B; ++b)
#pragma unroll
        for (int r = 0; r < 4; ++r)
            atomicAdd(&out[(size_t)b * N + n + r], acc[r][b]);
}

// ---------------- proven rm4 GEMV body (EXACT R4/R7), direct store ----------------
__device__ __forceinline__ void rm4_body(const float* __restrict__ x,
                                         const float* __restrict__ W,
                                         float* __restrict__ out, int N, int K,
                                         const float* __restrict__ addsrc,
                                         int n0, int lane) {
    int K4 = K >> 2;
    const float4* x4 = (const float4*)x;
    const float4* w0 = (const float4*)(W + (size_t)(n0 + 0) * K);
    const float4* w1 = (const float4*)(W + (size_t)(n0 + 1) * K);
    const float4* w2 = (const float4*)(W + (size_t)(n0 + 2) * K);
    const float4* w3 = (const float4*)(W + (size_t)(n0 + 3) * K);
    float acc[4][B];
#pragma unroll
    for (int r = 0; r < 4; ++r)
#pragma unroll
        for (int b = 0; b < B; ++b) acc[r][b] = 0.f;
#pragma unroll 2
    for (int i = lane; i < K4; i += 32) {
        float4 xv[B];
#pragma unroll
        for (int b = 0; b < B; ++b) xv[b] = x4[(size_t)b * K4 + i];
        float4 w;
        w = w0[i];
#pragma unroll
        for (int b = 0; b < B; ++b)
            acc[0][b] += w.x * xv[b].x + w.y * xv[b].y + w.z * xv[b].z + w.w * xv[b].w;
        w = w1[i];
#pragma unroll
        for (int b = 0; b < B; ++b)
            acc[1][b] += w.x * xv[b].x + w.y * xv[b].y + w.z * xv[b].z + w.w * xv[b].w;
        w = w2[i];
#pragma unroll
        for (int b = 0; b < B; ++b)
            acc[2][b] += w.x * xv[b].x + w.y * xv[b].y + w.z * xv[b].z + w.w * xv[b].w;
        w = w3[i];
#pragma unroll
        for (int b = 0; b < B; ++b)
            acc[3][b] += w.x * xv[b].x + w.y * xv[b].y + w.z * xv[b].z + w.w * xv[b].w;
    }
#pragma unroll
    for (int r = 0; r < 4; ++r)
#pragma unroll
        for (int b = 0; b < B; ++b)
#pragma unroll
            for (int off = 16; off > 0; off >>= 1)
                acc[r][b] += __shfl_xor_sync(0xffffffffu, acc[r][b], off);
    if (lane == 0) {
#pragma unroll
        for (int r = 0; r < 4; ++r) {
            int n = n0 + r;
            if (n < N) {
#pragma unroll
                for (int b = 0; b < B; ++b) {
                    float v = acc[r][b];
                    if (addsrc) v += addsrc[(size_t)b * N + n];
                    out[(size_t)b * N + n] = v;
                }
            }
        }
    }
}

// direct-store GEMV (wo, ffn2, gate)
__global__ void __launch_bounds__(256, 2)
gemv_rm4_kernel(const float* __restrict__ x, const float* __restrict__ W,
                float* __restrict__ out, int N, int K,
                const float* __restrict__ addsrc) {
    int warp = threadIdx.x >> 5, lane = threadIdx.x & 31;
    int n0 = (blockIdx.x * 8 + warp) * 4;
    if (n0 >= N) return;
    rm4_body(x, W, out, N, K, addsrc, n0, lane);
}

// ---------------- mega up-projection: ffn_w1|ffn_w3|moe_w1|moe_w3 in one grid ----------------
// rows: [0,2048)->t1, [2048,4096)->t3, [4096,12288)->h1 (moe_w1), [12288,20480)->h3 (moe_w3)
__global__ void __launch_bounds__(256, 2)
up_mega_kernel(const float* __restrict__ x,
               const float* __restrict__ fw1, const float* __restrict__ fw3,
               const float* __restrict__ mw1, const float* __restrict__ mw3,
               float* __restrict__ t1, float* __restrict__ t3,
               float* __restrict__ h1, float* __restrict__ h3,
               const float* __restrict__ wexp) {
    int warp = threadIdx.x >> 5, lane = threadIdx.x & 31;
    int row0 = (blockIdx.x * 8 + warp) * 4;
    const float* W;
    float* out;
    int n0, N;
    if (row0 < 2048)        { W = fw1; out = t1; n0 = row0;         N = FD; }
    else if (row0 < 4096)   { W = fw3; out = t3; n0 = row0 - 2048;  N = FD; }
    else if (row0 < 12288)  { W = mw1; out = h1; n0 = row0 - 4096;  N = E * FE; }
    else                    { W = mw3; out = h3; n0 = row0 - 12288; N = E * FE; }
    if (row0 >= 4096) {
        // expert skip: whole block belongs to one expert (boundaries multiple of 32)
        int e = n0 >> 10;
        bool any = false;
#pragma unroll
        for (int b = 0; b < B; ++b) any |= (wexp[b * E + e] != 0.f);
        if (!any) return;
    }
    rm4_body(x, W, out, N, DIM, nullptr, n0, lane);
}

// ---------------- MoE down-proj, expert skip, weighted atomic (R7) ----------------
__global__ void __launch_bounds__(256, 2)
moe_second4_kernel(const float* __restrict__ ge, const float* __restrict__ w2,
                   const float* __restrict__ wexp, float* __restrict__ out) {
    int e = blockIdx.y;
    __shared__ float we[B];
    if (threadIdx.x < B) we[threadIdx.x] = wexp[threadIdx.x * E + e];
    __syncthreads();
    bool any = false;
#pragma unroll
    for (int b = 0; b < B; ++b) any |= (we[b] != 0.f);
    if (!any) return;

    int warp = threadIdx.x >> 5, lane = threadIdx.x & 31;
    int n0 = (blockIdx.x * 8 + warp) * 4;
    const float4* x4 = (const float4*)ge;
    int K4 = FE >> 2;
    const float4* w0 = (const float4*)(w2 + ((size_t)e * DIM + n0 + 0) * FE);
    const float4* w1 = (const float4*)(w2 + ((size_t)e * DIM + n0 + 1) * FE);
    const float4* w2p = (const float4*)(w2 + ((size_t)e * DIM + n0 + 2) * FE);
    const float4* w3 = (const float4*)(w2 + ((size_t)e * DIM + n0 + 3) * FE);
    float acc[4][B];
#pragma unroll
    for (int r = 0; r < 4; ++r)
#pragma unroll
        for (int b = 0; b < B; ++b) acc[r][b] = 0.f;
#pragma unroll 2
    for (int i = lane; i < K4; i += 32) {
        float4 xv[B];
#pragma unroll
        for (int b = 0; b < B; ++b) xv[b] = x4[((size_t)b * E + e) * K4 + i];
        float4 w;
        w = w0[i];
#pragma unroll
        for (int b = 0; b < B; ++b)
            acc[0][b] += w.x * xv[b].x + w.y * xv[b].y + w.z * xv[b].z + w.w * xv[b].w;
        w = w1[i];
#pragma unroll
        for (int b = 0; b < B; ++b)
            acc[1][b] += w.x * xv[b].x + w.y * xv[b].y + w.z * xv[b].z + w.w * xv[b].w;
        w = w2p[i];
#pragma unroll
        for (int b = 0; b < B; ++b)
            acc[2][b] += w.x * xv[b].x + w.y * xv[b].y + w.z * xv[b].z + w.w * xv[b].w;
        w = w3[i];
#pragma unroll
        for (int b = 0; b < B; ++b)
            acc[3][b] += w.x * xv[b].x + w.y * xv[b].y + w.z * xv[b].z + w.w * xv[b].w;
    }
#pragma unroll
    for (int r = 0; r < 4; ++r)
#pragma unroll
        for (int b = 0; b < B; ++b)
#pragma unroll
            for (int off = 16; off > 0; off >>= 1)
                acc[r][b] += __shfl_xor_sync(0xffffffffu, acc[r][b], off);
    if (lane == 0) {
#pragma unroll
        for (int r = 0; r < 4; ++r) {
            int n = n0 + r;
#pragma unroll
            for (int b = 0; b < B; ++b)
                if (we[b] != 0.f) atomicAdd(&out[(size_t)b * DIM + n], we[b] * acc[r][b]);
        }
    }
}

// ---------------- rope + split ----------------
__global__ void rope_split_kernel(const float* __restrict__ qkv,
                                  const float* __restrict__ fc, const float* __restrict__ fs,
                                  float* __restrict__ q, float* __restrict__ knew,
                                  float* __restrict__ vnew) {
    int b = blockIdx.x;
    const float* qb = qkv + (size_t)b * QKV_N;
    for (int i = threadIdx.x; i < NH * 64; i += blockDim.x) {
        int h = i >> 6, pi = i & 63;
        int g = h >> 3, r = h & 7;
        const float* base = qb + g * 1280 + r * 128;
        float re = base[2 * pi], im = base[2 * pi + 1];
        float c = fc[pi], s = fs[pi];
        float* qo = q + ((size_t)b * NH + h) * HEAD_DIM;
        qo[2 * pi] = re * c - im * s;
        qo[2 * pi + 1] = re * s + im * c;
    }
    for (int i = threadIdx.x; i < N_KV * 64; i += blockDim.x) {
        int g = i >> 6, pi = i & 63;
        const float* base = qb + g * 1280 + 1024;
        float re = base[2 * pi], im = base[2 * pi + 1];
        float c = fc[pi], s = fs[pi];
        float* ko = knew + ((size_t)b * N_KV + g) * HEAD_DIM;
        ko[2 * pi] = re * c - im * s;
        ko[2 * pi + 1] = re * s + im * c;
    }
    for (int i = threadIdx.x; i < N_KV * HEAD_DIM; i += blockDim.x) {
        int g = i >> 7, d = i & 127;
        vnew[((size_t)b * N_KV + g) * HEAD_DIM + d] = qb[g * 1280 + 1152 + d];
    }
}

// ---------------- fused flash decode (R7 version, known-good 78us) ----------------
__global__ void __launch_bounds__(256, 4)
flash_decode_kernel(const float* __restrict__ q, const float* __restrict__ cache_k,
                    const float* __restrict__ cache_v,
                    const float* __restrict__ knew, const float* __restrict__ vnew,
                    const float* __restrict__ mask, const int* __restrict__ sp_ptr,
                    float* __restrict__ part_o, float* __restrict__ part_m,
                    float* __restrict__ part_l) {
    int split = blockIdx.x, g = blockIdx.y, b = blockIdx.z;
    int sp = *sp_ptr;
    int warp = threadIdx.x >> 5, lane = threadIdx.x & 31;
    int j0 = split * JSPL;

    __shared__ __align__(16) float s[8][JSPL + 4];
    __shared__ float wmax[8][8];

    float4 q4[8];
    const float* qb = q + ((size_t)b * NH + g * 8) * HEAD_DIM;
#pragma unroll
    for (int r = 0; r < 8; ++r)
        q4[r] = ((const float4*)(qb + r * HEAD_DIM))[lane];

    const float scale = 0.08838834764831845f;
    float mloc = -1e30f;

    for (int jj = 0; jj < JWARP; ++jj) {
        int jl = warp * JWARP + jj;
        int j = j0 + jl;
        const float4* krow = (const float4*)((j == sp)
            ? (knew + ((size_t)b * N_KV + g) * HEAD_DIM)
            : (cache_k + (((size_t)b * KV + j) * N_KV + g) * HEAD_DIM));
        float4 k4 = krow[lane];
        float p[8];
#pragma unroll
        for (int r = 0; r < 8; ++r)
            p[r] = k4.x * q4[r].x + k4.y * q4[r].y + k4.z * q4[r].z + k4.w * q4[r].w;
#pragma unroll
        for (int k = 0; k < 4; ++k) {
            float a = p[2 * k], bb = p[2 * k + 1];
            float t = (lane & 1) ? a : bb;
            t = __shfl_xor_sync(0xffffffffu, t, 1);
            p[k] = ((lane & 1) ? bb : a) + t;
        }
#pragma unroll
        for (int k = 0; k < 2; ++k) {
            float a = p[2 * k], bb = p[2 * k + 1];
            float t = (lane & 2) ? a : bb;
            t = __shfl_xor_sync(0xffffffffu, t, 2);
            p[k] = ((lane & 2) ? bb : a) + t;
        }
        {
            float a = p[0], bb = p[1];
            float t = (lane & 4) ? a : bb;
            t = __shfl_xor_sync(0xffffffffu, t, 4);
            p[0] = ((lane & 4) ? bb : a) + t;
        }
        float v = p[0];
        v += __shfl_xor_sync(0xffffffffu, v, 8);
        v += __shfl_xor_sync(0xffffffffu, v, 16);
        if (lane < 8) {
            float sc = v * scale + mask[j];
            s[lane][jl] = sc;
            mloc = fmaxf(mloc, sc);
        }
    }
    if (lane < 8) wmax[warp][lane] = mloc;
    __syncthreads();

    {
        int r = warp;
        float m = wmax[0][r];
#pragma unroll
        for (int w = 1; w < 8; ++w) m = fmaxf(m, wmax[w][r]);
        float ls = 0.f;
        for (int jl = lane; jl < JSPL; jl += 32) {
            float pv = __expf(s[r][jl] - m);
            s[r][jl] = pv;
            ls += pv;
        }
#pragma unroll
        for (int off = 16; off > 0; off >>= 1) ls += __shfl_xor_sync(0xffffffffu, ls, off);
        if (lane == 0) {
            int idx = ((b * N_KV + g) * SPLITS + split) * N_REP + r;
            part_m[idx] = m;
            part_l[idx] = ls;
        }
    }
    __syncthreads();

    float4 acc[8];
#pragma unroll
    for (int r = 0; r < 8; ++r) acc[r] = make_float4(0.f, 0.f, 0.f, 0.f);
    for (int jj = 0; jj < JWARP; ++jj) {
        int jl = warp * JWARP + jj;
        int j = j0 + jl;
        const float4* vrow = (const float4*)((j == sp)
            ? (vnew + ((size_t)b * N_KV + g) * HEAD_DIM)
            : (cache_v + (((size_t)b * KV + j) * N_KV + g) * HEAD_DIM));
        float4 v4 = vrow[lane];
#pragma unroll
        for (int r = 0; r < 8; ++r) {
            float pr = s[r][jl];
            acc[r].x += pr * v4.x;
            acc[r].y += pr * v4.y;
            acc[r].z += pr * v4.z;
            acc[r].w += pr * v4.w;
        }
    }

    float4* sb = (float4*)&s[0][0];
    float* po = part_o + (((size_t)(b * N_KV + g) * SPLITS + split) * N_REP) * HEAD_DIM;
#pragma unroll
    for (int rg = 0; rg < 4; ++rg) {
        __syncthreads();
        sb[(warp * 2 + 0) * 32 + lane] = acc[rg * 2 + 0];
        sb[(warp * 2 + 1) * 32 + lane] = acc[rg * 2 + 1];
        __syncthreads();
        int rrl = threadIdx.x >> 7;
        int d = threadIdx.x & 127;
        float v = 0.f;
        const float* sf = (const float*)sb;
#pragma unroll
        for (int w = 0; w < 8; ++w)
            v += sf[(w * 2 + rrl) * 128 + d];
        po[(rg * 2 + rrl) * HEAD_DIM + d] = v;
    }
}

// ---------------- combine splits ----------------
__global__ void combine_kernel(const float* __restrict__ part_o, const float* __restrict__ part_m,
                               const float* __restrict__ part_l, float* __restrict__ attn) {
    int head = blockIdx.x & 63, b = blockIdx.x >> 6;
    int g = head >> 3, r = head & 7;
    int d = threadIdx.x;
    float M = -1e30f;
#pragma unroll
    for (int sp = 0; sp < SPLITS; ++sp)
        M = fmaxf(M, part_m[((b * N_KV + g) * SPLITS + sp) * N_REP + r]);
    float L = 0.f, acc = 0.f;
#pragma unroll
    for (int sp = 0; sp < SPLITS; ++sp) {
        int idx = ((b * N_KV + g) * SPLITS + sp) * N_REP + r;
        float w = __expf(part_m[idx] - M);
        L += w * part_l[idx];
        acc += w * part_o[(((size_t)(b * N_KV + g) * SPLITS + sp) * N_REP + r) * HEAD_DIM + d];
    }
    attn[((size_t)b * NH + head) * HEAD_DIM + d] = acc / L;
}

// ---------------- gelu(t1)*t3 ----------------
__global__ void gelumul_kernel(const float* __restrict__ t1, const float* __restrict__ t3,
                               float* __restrict__ g, int n) {
    int i = blockIdx.x * blockDim.x + threadIdx.x;
    if (i < n) {
        float x = t1[i];
        g[i] = 0.5f * x * (1.f + erff(x * 0.7071067811865476f)) * t3[i];
    }
}

// ---------------- gate softmax + top-2 ----------------
__global__ void gate_topk_kernel(const float* __restrict__ logits, float* __restrict__ wexp) {
    int b = threadIdx.x;
    if (b >= B) return;
    float l[E];
    float m = -1e30f;
#pragma unroll
    for (int e = 0; e < E; ++e) { l[e] = logits[b * E + e]; m = fmaxf(m, l[e]); }
    float sum = 0.f;
#pragma unroll
    for (int e = 0; e < E; ++e) { l[e] = expf(l[e] - m); sum += l[e]; }
#pragma unroll
    for (int e = 0; e < E; ++e) l[e] /= sum;
    int i1 = 0;
#pragma unroll
    for (int e = 1; e < E; ++e) if (l[e] > l[i1]) i1 = e;
    int i2 = (i1 == 0) ? 1 : 0;
#pragma unroll
    for (int e = 0; e < E; ++e) if (e != i1 && l[e] > l[i2]) i2 = e;
#pragma unroll
    for (int e = 0; e < E; ++e)
        wexp[b * E + e] = (e == i1) ? l[i1] : (e == i2) ? l[i2] : 0.f;
}

// ---------------- launch ----------------
extern "C" void kernel_launch(void* const* d_in, const int* in_sizes, int n_in,
                              void* d_out, int out_size) {
    const float* x        = (const float*)d_in[0];
    const float* mask     = (const float*)d_in[1];
    const float* fcos     = (const float*)d_in[2];
    const float* fsin     = (const float*)d_in[3];
    const float* cache_k  = (const float*)d_in[4];
    const float* cache_v  = (const float*)d_in[5];
    const float* wqkv     = (const float*)d_in[6];
    const float* wo       = (const float*)d_in[7];
    const float* attn_nw  = (const float*)d_in[8];
    const float* ffn_nw   = (const float*)d_in[9];
    const float* ffn_w1   = (const float*)d_in[10];
    const float* ffn_w2   = (const float*)d_in[11];
    const float* ffn_w3   = (const float*)d_in[12];
    const float* gate_w   = (const float*)d_in[13];
    const float* moe_w1   = (const float*)d_in[14];
    const float* moe_w2   = (const float*)d_in[15];
    const float* moe_w3   = (const float*)d_in[16];
    const int*   sp       = (const int*)d_in[17];
    float* out            = (float*)d_out;

    float *an, *qkv, *q, *knew, *vnew, *attn, *h, *fin, *t1, *t3, *gg;
    float *glog, *wexp, *h1, *h3, *ge, *po, *pm, *pl;
    cudaGetSymbolAddress((void**)&an, g_an);
    cudaGetSymbolAddress((void**)&qkv, g_qkv);
    cudaGetSymbolAddress((void**)&q, g_q);
    cudaGetSymbolAddress((void**)&knew, g_knew);
    cudaGetSymbolAddress((void**)&vnew, g_vnew);
    cudaGetSymbolAddress((void**)&attn, g_attn);
    cudaGetSymbolAddress((void**)&h, g_h);
    cudaGetSymbolAddress((void**)&fin, g_fin);
    cudaGetSymbolAddress((void**)&t1, g_t1);
    cudaGetSymbolAddress((void**)&t3, g_t3);
    cudaGetSymbolAddress((void**)&gg, g_g);
    cudaGetSymbolAddress((void**)&glog, g_glog);
    cudaGetSymbolAddress((void**)&wexp, g_wexp);
    cudaGetSymbolAddress((void**)&h1, g_h1);
    cudaGetSymbolAddress((void**)&h3, g_h3);
    cudaGetSymbolAddress((void**)&ge, g_ge);
    cudaGetSymbolAddress((void**)&po, g_part_o);
    cudaGetSymbolAddress((void**)&pm, g_part_m);
    cudaGetSymbolAddress((void**)&pl, g_part_l);

    cudaMemsetAsync(qkv, 0, sizeof(float) * B * QKV_N);

    // attention
    rmsnorm_kernel<<<B, 1024>>>(x, attn_nw, an);
    gemv_cm4_kernel<<<dim3((QKV_N / 4) / 128, 32), 128>>>(an, wqkv, qkv, DIM, QKV_N, DIM / 32);
    rope_split_kernel<<<B, 512>>>(qkv, fcos, fsin, q, knew, vnew);
    flash_decode_kernel<<<dim3(SPLITS, N_KV, B), 256>>>(q, cache_k, cache_v, knew, vnew,
                                                        mask, sp, po, pm, pl);
    combine_kernel<<<B * NH, HEAD_DIM>>>(po, pm, pl, attn);
    gemv_rm4_kernel<<<DIM / 32, 256>>>(attn, wo, h, DIM, DIM, x);   // h = x + attn@wo.T

    // ffn + moe
    rmsnorm_kernel<<<B, 1024>>>(h, ffn_nw, fin);
    gemv_rm4_kernel<<<1, 256>>>(fin, gate_w, glog, E, DIM, nullptr);
    gate_topk_kernel<<<1, 32>>>(glog, wexp);
    // mega: ffn_w1 -> t1, ffn_w3 -> t3, moe_w1 -> h1, moe_w3 -> h3 (one 640-block launch)
    up_mega_kernel<<<(2 * FD + 2 * E * FE) / 32, 256>>>(fin, ffn_w1, ffn_w3, moe_w1, moe_w3,
                                                        t1, t3, h1, h3, wexp);
    gelumul_kernel<<<(B * FD) / 256, 256>>>(t1, t3, gg, B * FD);
    gelumul_kernel<<<(B * E * FE) / 256, 256>>>(h1, h3, ge, B * E * FE);
    gemv_rm4_kernel<<<DIM / 32, 256>>>(gg, ffn_w2, out, DIM, FD, h);  // out = h + ff
    moe_second4_kernel<<<dim3(DIM / 32, E), 256>>>(ge, moe_w2, wexp, out);  // out += moe
}

// round 13
// speedup vs baseline: 1.3050x; 1.3050x over previous
#include <cuda_runtime.h>
#include <cuda_bf16.h>
#include <math.h>

#define B 8
#define DIM 8192
#define HEAD_DIM 128
#define N_KV 8
#define N_REP 8
#define NH 64
#define KV 4096
#define E 8
#define FD 2048
#define FE 1024
#define QKV_N 10240
#define SPLITS 16
#define JSPL (KV / SPLITS)   /* 256 */
#define JWARP (JSPL / 8)     /* 32  */

// ---------------- scratch ----------------
__device__ float g_an[B * DIM];
__device__ float g_qkv[B * QKV_N];
__device__ float g_q[B * NH * HEAD_DIM];
__device__ float g_knew[B * N_KV * HEAD_DIM];
__device__ float g_vnew[B * N_KV * HEAD_DIM];
__device__ float g_attn[B * DIM];
__device__ float g_h[B * DIM];
__device__ float g_fin[B * DIM];
__device__ float g_t1[B * FD];
__device__ float g_t3[B * FD];
__device__ float g_g[B * FD];
__device__ float g_glog[B * E];
__device__ float g_wexp[B * E];
__device__ float g_h1[B * E * FE];
__device__ float g_h3[B * E * FE];
__device__ float g_ge[B * E * FE];
__device__ float g_part_o[(size_t)B * N_KV * SPLITS * N_REP * HEAD_DIM];
__device__ float g_part_m[B * N_KV * SPLITS * N_REP];
__device__ float g_part_l[B * N_KV * SPLITS * N_REP];

// ---------------- rmsnorm ----------------
__global__ void rmsnorm_kernel(const float* __restrict__ x, const float* __restrict__ w,
                               float* __restrict__ out) {
    int b = blockIdx.x;
    const float* xb = x + (size_t)b * DIM;
    float* ob = out + (size_t)b * DIM;
    float ss = 0.f;
    for (int i = threadIdx.x; i < DIM; i += blockDim.x) {
        float v = xb[i];
        ss += v * v;
    }
    __shared__ float red[32];
    for (int off = 16; off > 0; off >>= 1) ss += __shfl_xor_sync(0xffffffffu, ss, off);
    int lane = threadIdx.x & 31, warp = threadIdx.x >> 5;
    if (lane == 0) red[warp] = ss;
    __syncthreads();
    if (warp == 0) {
        float v = (lane < (int)(blockDim.x >> 5)) ? red[lane] : 0.f;
        for (int off = 16; off > 0; off >>= 1) v += __shfl_xor_sync(0xffffffffu, v, off);
        if (lane == 0) red[0] = v;
    }
    __syncthreads();
    float scale = rsqrtf(red[0] / (float)DIM + 1e-5f);
    for (int i = threadIdx.x; i < DIM; i += blockDim.x)
        ob[i] = xb[i] * scale * w[i];
}

// ---------------- column-major GEMV (x[B,K] @ W[K,N]), k-split + atomics (R7) ----------------
__global__ void __launch_bounds__(128, 4)
gemv_cm4_kernel(const float* __restrict__ x, const float* __restrict__ W,
                float* __restrict__ out, int K, int N, int kchunk) {
    int n4 = blockIdx.x * blockDim.x + threadIdx.x;
    int N4 = N >> 2;
    int k0 = blockIdx.y * kchunk;
    __shared__ float xs[B][128];
    float acc[4][B];
#pragma unroll
    for (int r = 0; r < 4; ++r)
#pragma unroll
        for (int b = 0; b < B; ++b) acc[r][b] = 0.f;
    const float4* W4 = (const float4*)W;
    for (int kb = k0; kb < k0 + kchunk; kb += 128) {
        __syncthreads();
        for (int i = threadIdx.x; i < B * 128; i += blockDim.x)
            xs[i >> 7][i & 127] = x[(size_t)(i >> 7) * K + kb + (i & 127)];
        __syncthreads();
#pragma unroll 8
        for (int kk = 0; kk < 128; ++kk) {
            float4 w = W4[(size_t)(kb + kk) * N4 + n4];
#pragma unroll
            for (int b = 0; b < B; ++b) {
                float xv = xs[b][kk];
                acc[0][b] += w.x * xv;
                acc[1][b] += w.y * xv;
                acc[2][b] += w.z * xv;
                acc[3][b] += w.w * xv;
            }
        }
    }
    int n = n4 * 4;
#pragma unroll
    for (int b = 0; b < B; ++b)
#pragma unroll
        for (int r = 0; r < 4; ++r)
            atomicAdd(&out[(size_t)b * N + n + r], acc[r][b]);
}

// ---------------- proven rm4 GEMV body (EXACT R4/R7 inner loop) ----------------
__device__ __forceinline__ void rm4_body(const float* __restrict__ x,
                                         const float* __restrict__ W,
                                         float* __restrict__ out, int N, int K,
                                         const float* __restrict__ addsrc,
                                         int n0, int lane) {
    int K4 = K >> 2;
    const float4* x4 = (const float4*)x;
    const float4* w0 = (const float4*)(W + (size_t)(n0 + 0) * K);
    const float4* w1 = (const float4*)(W + (size_t)(n0 + 1) * K);
    const float4* w2 = (const float4*)(W + (size_t)(n0 + 2) * K);
    const float4* w3 = (const float4*)(W + (size_t)(n0 + 3) * K);
    float acc[4][B];
#pragma unroll
    for (int r = 0; r < 4; ++r)
#pragma unroll
        for (int b = 0; b < B; ++b) acc[r][b] = 0.f;
#pragma unroll 2
    for (int i = lane; i < K4; i += 32) {
        float4 xv[B];
#pragma unroll
        for (int b = 0; b < B; ++b) xv[b] = x4[(size_t)b * K4 + i];
        float4 w;
        w = w0[i];
#pragma unroll
        for (int b = 0; b < B; ++b)
            acc[0][b] += w.x * xv[b].x + w.y * xv[b].y + w.z * xv[b].z + w.w * xv[b].w;
        w = w1[i];
#pragma unroll
        for (int b = 0; b < B; ++b)
            acc[1][b] += w.x * xv[b].x + w.y * xv[b].y + w.z * xv[b].z + w.w * xv[b].w;
        w = w2[i];
#pragma unroll
        for (int b = 0; b < B; ++b)
            acc[2][b] += w.x * xv[b].x + w.y * xv[b].y + w.z * xv[b].z + w.w * xv[b].w;
        w = w3[i];
#pragma unroll
        for (int b = 0; b < B; ++b)
            acc[3][b] += w.x * xv[b].x + w.y * xv[b].y + w.z * xv[b].z + w.w * xv[b].w;
    }
#pragma unroll
    for (int r = 0; r < 4; ++r)
#pragma unroll
        for (int b = 0; b < B; ++b)
#pragma unroll
            for (int off = 16; off > 0; off >>= 1)
                acc[r][b] += __shfl_xor_sync(0xffffffffu, acc[r][b], off);
    if (lane == 0) {
#pragma unroll
        for (int r = 0; r < 4; ++r) {
            int n = n0 + r;
            if (n < N) {
#pragma unroll
                for (int b = 0; b < B; ++b) {
                    float v = acc[r][b];
                    if (addsrc) v += addsrc[(size_t)b * N + n];
                    out[(size_t)b * N + n] = v;
                }
            }
        }
    }
}

// direct-store GEMV — 128-thread blocks, same 64K-reg budget as (256,2)
__global__ void __launch_bounds__(128, 4)
gemv_rm4_kernel(const float* __restrict__ x, const float* __restrict__ W,
                float* __restrict__ out, int N, int K,
                const float* __restrict__ addsrc) {
    int warp = threadIdx.x >> 5, lane = threadIdx.x & 31;
    int n0 = (blockIdx.x * 4 + warp) * 4;
    if (n0 >= N) return;
    rm4_body(x, W, out, N, K, addsrc, n0, lane);
}

// dual (Wa,Wb via blockIdx.z) + k-split (gridDim.y) atomic; outputs pre-zeroed
__global__ void __launch_bounds__(128, 4)
gemv_rm4_dual_atomic_kernel(const float* __restrict__ x,
                            const float* __restrict__ Wa, const float* __restrict__ Wb,
                            float* __restrict__ outa, float* __restrict__ outb,
                            int N, int K) {
    const float* W = (blockIdx.z == 0) ? Wa : Wb;
    float* out = (blockIdx.z == 0) ? outa : outb;
    int warp = threadIdx.x >> 5, lane = threadIdx.x & 31;
    int n0 = (blockIdx.x * 4 + warp) * 4;
    if (n0 >= N) return;
    int K4 = K >> 2;
    int chunk = K4 / gridDim.y;
    int i0 = blockIdx.y * chunk;
    const float4* x4 = (const float4*)x;
    const float4* w0 = (const float4*)(W + (size_t)(n0 + 0) * K);
    const float4* w1 = (const float4*)(W + (size_t)(n0 + 1) * K);
    const float4* w2 = (const float4*)(W + (size_t)(n0 + 2) * K);
    const float4* w3 = (const float4*)(W + (size_t)(n0 + 3) * K);
    float acc[4][B];
#pragma unroll
    for (int r = 0; r < 4; ++r)
#pragma unroll
        for (int b = 0; b < B; ++b) acc[r][b] = 0.f;
#pragma unroll 2
    for (int i = i0 + lane; i < i0 + chunk; i += 32) {
        float4 xv[B];
#pragma unroll
        for (int b = 0; b < B; ++b) xv[b] = x4[(size_t)b * K4 + i];
        float4 w;
        w = w0[i];
#pragma unroll
        for (int b = 0; b < B; ++b)
            acc[0][b] += w.x * xv[b].x + w.y * xv[b].y + w.z * xv[b].z + w.w * xv[b].w;
        w = w1[i];
#pragma unroll
        for (int b = 0; b < B; ++b)
            acc[1][b] += w.x * xv[b].x + w.y * xv[b].y + w.z * xv[b].z + w.w * xv[b].w;
        w = w2[i];
#pragma unroll
        for (int b = 0; b < B; ++b)
            acc[2][b] += w.x * xv[b].x + w.y * xv[b].y + w.z * xv[b].z + w.w * xv[b].w;
        w = w3[i];
#pragma unroll
        for (int b = 0; b < B; ++b)
            acc[3][b] += w.x * xv[b].x + w.y * xv[b].y + w.z * xv[b].z + w.w * xv[b].w;
    }
#pragma unroll
    for (int r = 0; r < 4; ++r)
#pragma unroll
        for (int b = 0; b < B; ++b)
#pragma unroll
            for (int off = 16; off > 0; off >>= 1)
                acc[r][b] += __shfl_xor_sync(0xffffffffu, acc[r][b], off);
    if (lane == 0) {
#pragma unroll
        for (int r = 0; r < 4; ++r)
#pragma unroll
            for (int b = 0; b < B; ++b)
                atomicAdd(&out[(size_t)b * N + n0 + r], acc[r][b]);
    }
}

// MoE up: dual (w1,w3), expert skip, direct store — 128-thread blocks
__global__ void __launch_bounds__(128, 4)
moe_up_dual_kernel(const float* __restrict__ x,
                   const float* __restrict__ W1, const float* __restrict__ W3,
                   float* __restrict__ o1, float* __restrict__ o3,
                   const float* __restrict__ wexp) {
    int warp = threadIdx.x >> 5, lane = threadIdx.x & 31;
    int n0 = (blockIdx.x * 4 + warp) * 4;
    int e = n0 >> 10;   // FE = 1024; block's 16 rows stay within one expert
    __shared__ float we[B];
    if (threadIdx.x < B) we[threadIdx.x] = wexp[threadIdx.x * E + e];
    __syncthreads();
    bool any = false;
#pragma unroll
    for (int b = 0; b < B; ++b) any |= (we[b] != 0.f);
    if (!any) return;
    const float* W = (blockIdx.z == 0) ? W1 : W3;
    float* out = (blockIdx.z == 0) ? o1 : o3;
    rm4_body(x, W, out, E * FE, DIM, nullptr, n0, lane);
}

// MoE down-proj, expert skip, weighted atomic — 128-thread blocks
__global__ void __launch_bounds__(128, 4)
moe_second4_kernel(const float* __restrict__ ge, const float* __restrict__ w2,
                   const float* __restrict__ wexp, float* __restrict__ out) {
    int e = blockIdx.y;
    __shared__ float we[B];
    if (threadIdx.x < B) we[threadIdx.x] = wexp[threadIdx.x * E + e];
    __syncthreads();
    bool any = false;
#pragma unroll
    for (int b = 0; b < B; ++b) any |= (we[b] != 0.f);
    if (!any) return;

    int warp = threadIdx.x >> 5, lane = threadIdx.x & 31;
    int n0 = (blockIdx.x * 4 + warp) * 4;
    const float4* x4 = (const float4*)ge;
    int K4 = FE >> 2;
    const float4* w0 = (const float4*)(w2 + ((size_t)e * DIM + n0 + 0) * FE);
    const float4* w1 = (const float4*)(w2 + ((size_t)e * DIM + n0 + 1) * FE);
    const float4* w2p = (const float4*)(w2 + ((size_t)e * DIM + n0 + 2) * FE);
    const float4* w3 = (const float4*)(w2 + ((size_t)e * DIM + n0 + 3) * FE);
    float acc[4][B];
#pragma unroll
    for (int r = 0; r < 4; ++r)
#pragma unroll
        for (int b = 0; b < B; ++b) acc[r][b] = 0.f;
#pragma unroll 2
    for (int i = lane; i < K4; i += 32) {
        float4 xv[B];
#pragma unroll
        for (int b = 0; b < B; ++b) xv[b] = x4[((size_t)b * E + e) * K4 + i];
        float4 w;
        w = w0[i];
#pragma unroll
        for (int b = 0; b < B; ++b)
            acc[0][b] += w.x * xv[b].x + w.y * xv[b].y + w.z * xv[b].z + w.w * xv[b].w;
        w = w1[i];
#pragma unroll
        for (int b = 0; b < B; ++b)
            acc[1][b] += w.x * xv[b].x + w.y * xv[b].y + w.z * xv[b].z + w.w * xv[b].w;
        w = w2p[i];
#pragma unroll
        for (int b = 0; b < B; ++b)
            acc[2][b] += w.x * xv[b].x + w.y * xv[b].y + w.z * xv[b].z + w.w * xv[b].w;
        w = w3[i];
#pragma unroll
        for (int b = 0; b < B; ++b)
            acc[3][b] += w.x * xv[b].x + w.y * xv[b].y + w.z * xv[b].z + w.w * xv[b].w;
    }
#pragma unroll
    for (int r = 0; r < 4; ++r)
#pragma unroll
        for (int b = 0; b < B; ++b)
#pragma unroll
            for (int off = 16; off > 0; off >>= 1)
                acc[r][b] += __shfl_xor_sync(0xffffffffu, acc[r][b], off);
    if (lane == 0) {
#pragma unroll
        for (int r = 0; r < 4; ++r) {
            int n = n0 + r;
#pragma unroll
            for (int b = 0; b < B; ++b)
                if (we[b] != 0.f) atomicAdd(&out[(size_t)b * DIM + n], we[b] * acc[r][b]);
        }
    }
}

// ---------------- rope + split ----------------
__global__ void rope_split_kernel(const float* __restrict__ qkv,
                                  const float* __restrict__ fc, const float* __restrict__ fs,
                                  float* __restrict__ q, float* __restrict__ knew,
                                  float* __restrict__ vnew) {
    int b = blockIdx.x;
    const float* qb = qkv + (size_t)b * QKV_N;
    for (int i = threadIdx.x; i < NH * 64; i += blockDim.x) {
        int h = i >> 6, pi = i & 63;
        int g = h >> 3, r = h & 7;
        const float* base = qb + g * 1280 + r * 128;
        float re = base[2 * pi], im = base[2 * pi + 1];
        float c = fc[pi], s = fs[pi];
        float* qo = q + ((size_t)b * NH + h) * HEAD_DIM;
        qo[2 * pi] = re * c - im * s;
        qo[2 * pi + 1] = re * s + im * c;
    }
    for (int i = threadIdx.x; i < N_KV * 64; i += blockDim.x) {
        int g = i >> 6, pi = i & 63;
        const float* base = qb + g * 1280 + 1024;
        float re = base[2 * pi], im = base[2 * pi + 1];
        float c = fc[pi], s = fs[pi];
        float* ko = knew + ((size_t)b * N_KV + g) * HEAD_DIM;
        ko[2 * pi] = re * c - im * s;
        ko[2 * pi + 1] = re * s + im * c;
    }
    for (int i = threadIdx.x; i < N_KV * HEAD_DIM; i += blockDim.x) {
        int g = i >> 7, d = i & 127;
        vnew[((size_t)b * N_KV + g) * HEAD_DIM + d] = qb[g * 1280 + 1152 + d];
    }
}

// ---------------- fused flash decode (R7 version, known-good) ----------------
__global__ void __launch_bounds__(256, 4)
flash_decode_kernel(const float* __restrict__ q, const float* __restrict__ cache_k,
                    const float* __restrict__ cache_v,
                    const float* __restrict__ knew, const float* __restrict__ vnew,
                    const float* __restrict__ mask, const int* __restrict__ sp_ptr,
                    float* __restrict__ part_o, float* __restrict__ part_m,
                    float* __restrict__ part_l) {
    int split = blockIdx.x, g = blockIdx.y, b = blockIdx.z;
    int sp = *sp_ptr;
    int warp = threadIdx.x >> 5, lane = threadIdx.x & 31;
    int j0 = split * JSPL;

    __shared__ __align__(16) float s[8][JSPL + 4];
    __shared__ float wmax[8][8];

    float4 q4[8];
    const float* qb = q + ((size_t)b * NH + g * 8) * HEAD_DIM;
#pragma unroll
    for (int r = 0; r < 8; ++r)
        q4[r] = ((const float4*)(qb + r * HEAD_DIM))[lane];

    const float scale = 0.08838834764831845f;
    float mloc = -1e30f;

    for (int jj = 0; jj < JWARP; ++jj) {
        int jl = warp * JWARP + jj;
        int j = j0 + jl;
        const float4* krow = (const float4*)((j == sp)
            ? (knew + ((size_t)b * N_KV + g) * HEAD_DIM)
            : (cache_k + (((size_t)b * KV + j) * N_KV + g) * HEAD_DIM));
        float4 k4 = krow[lane];
        float p[8];
#pragma unroll
        for (int r = 0; r < 8; ++r)
            p[r] = k4.x * q4[r].x + k4.y * q4[r].y + k4.z * q4[r].z + k4.w * q4[r].w;
#pragma unroll
        for (int k = 0; k < 4; ++k) {
            float a = p[2 * k], bb = p[2 * k + 1];
            float t = (lane & 1) ? a : bb;
            t = __shfl_xor_sync(0xffffffffu, t, 1);
            p[k] = ((lane & 1) ? bb : a) + t;
        }
#pragma unroll
        for (int k = 0; k < 2; ++k) {
            float a = p[2 * k], bb = p[2 * k + 1];
            float t = (lane & 2) ? a : bb;
            t = __shfl_xor_sync(0xffffffffu, t, 2);
            p[k] = ((lane & 2) ? bb : a) + t;
        }
        {
            float a = p[0], bb = p[1];
            float t = (lane & 4) ? a : bb;
            t = __shfl_xor_sync(0xffffffffu, t, 4);
            p[0] = ((lane & 4) ? bb : a) + t;
        }
        float v = p[0];
        v += __shfl_xor_sync(0xffffffffu, v, 8);
        v += __shfl_xor_sync(0xffffffffu, v, 16);
        if (lane < 8) {
            float sc = v * scale + mask[j];
            s[lane][jl] = sc;
            mloc = fmaxf(mloc, sc);
        }
    }
    if (lane < 8) wmax[warp][lane] = mloc;
    __syncthreads();

    {
        int r = warp;
        float m = wmax[0][r];
#pragma unroll
        for (int w = 1; w < 8; ++w) m = fmaxf(m, wmax[w][r]);
        float ls = 0.f;
        for (int jl = lane; jl < JSPL; jl += 32) {
            float pv = __expf(s[r][jl] - m);
            s[r][jl] = pv;
            ls += pv;
        }
#pragma unroll
        for (int off = 16; off > 0; off >>= 1) ls += __shfl_xor_sync(0xffffffffu, ls, off);
        if (lane == 0) {
            int idx = ((b * N_KV + g) * SPLITS + split) * N_REP + r;
            part_m[idx] = m;
            part_l[idx] = ls;
        }
    }
    __syncthreads();

    float4 acc[8];
#pragma unroll
    for (int r = 0; r < 8; ++r) acc[r] = make_float4(0.f, 0.f, 0.f, 0.f);
    for (int jj = 0; jj < JWARP; ++jj) {
        int jl = warp * JWARP + jj;
        int j = j0 + jl;
        const float4* vrow = (const float4*)((j == sp)
            ? (vnew + ((size_t)b * N_KV + g) * HEAD_DIM)
            : (cache_v + (((size_t)b * KV + j) * N_KV + g) * HEAD_DIM));
        float4 v4 = vrow[lane];
#pragma unroll
        for (int r = 0; r < 8; ++r) {
            float pr = s[r][jl];
            acc[r].x += pr * v4.x;
            acc[r].y += pr * v4.y;
            acc[r].z += pr * v4.z;
            acc[r].w += pr * v4.w;
        }
    }

    float4* sb = (float4*)&s[0][0];
    float* po = part_o + (((size_t)(b * N_KV + g) * SPLITS + split) * N_REP) * HEAD_DIM;
#pragma unroll
    for (int rg = 0; rg < 4; ++rg) {
        __syncthreads();
        sb[(warp * 2 + 0) * 32 + lane] = acc[rg * 2 + 0];
        sb[(warp * 2 + 1) * 32 + lane] = acc[rg * 2 + 1];
        __syncthreads();
        int rrl = threadIdx.x >> 7;
        int d = threadIdx.x & 127;
        float v = 0.f;
        const float* sf = (const float*)sb;
#pragma unroll
        for (int w = 0; w < 8; ++w)
            v += sf[(w * 2 + rrl) * 128 + d];
        po[(rg * 2 + rrl) * HEAD_DIM + d] = v;
    }
}

// ---------------- combine splits ----------------
__global__ void combine_kernel(const float* __restrict__ part_o, const float* __restrict__ part_m,
                               const float* __restrict__ part_l, float* __restrict__ attn) {
    int head = blockIdx.x & 63, b = blockIdx.x >> 6;
    int g = head >> 3, r = head & 7;
    int d = threadIdx.x;
    float M = -1e30f;
#pragma unroll
    for (int sp = 0; sp < SPLITS; ++sp)
        M = fmaxf(M, part_m[((b * N_KV + g) * SPLITS + sp) * N_REP + r]);
    float L = 0.f, acc = 0.f;
#pragma unroll
    for (int sp = 0; sp < SPLITS; ++sp) {
        int idx = ((b * N_KV + g) * SPLITS + sp) * N_REP + r;
        float w = __expf(part_m[idx] - M);
        L += w * part_l[idx];
        acc += w * part_o[(((size_t)(b * N_KV + g) * SPLITS + sp) * N_REP + r) * HEAD_DIM + d];
    }
    attn[((size_t)b * NH + head) * HEAD_DIM + d] = acc / L;
}

// ---------------- gelu(t1)*t3 ----------------
__global__ void gelumul_kernel(const float* __restrict__ t1, const float* __restrict__ t3,
                               float* __restrict__ g, int n) {
    int i = blockIdx.x * blockDim.x + threadIdx.x;
    if (i < n) {
        float x = t1[i];
        g[i] = 0.5f * x * (1.f + erff(x * 0.7071067811865476f)) * t3[i];
    }
}

// ---------------- gate softmax + top-2 ----------------
__global__ void gate_topk_kernel(const float* __restrict__ logits, float* __restrict__ wexp) {
    int b = threadIdx.x;
    if (b >= B) return;
    float l[E];
    float m = -1e30f;
#pragma unroll
    for (int e = 0; e < E; ++e) { l[e] = logits[b * E + e]; m = fmaxf(m, l[e]); }
    float sum = 0.f;
#pragma unroll
    for (int e = 0; e < E; ++e) { l[e] = expf(l[e] - m); sum += l[e]; }
#pragma unroll
    for (int e = 0; e < E; ++e) l[e] /= sum;
    int i1 = 0;
#pragma unroll
    for (int e = 1; e < E; ++e) if (l[e] > l[i1]) i1 = e;
    int i2 = (i1 == 0) ? 1 : 0;
#pragma unroll
    for (int e = 0; e < E; ++e) if (e != i1 && l[e] > l[i2]) i2 = e;
#pragma unroll
    for (int e = 0; e < E; ++e)
        wexp[b * E + e] = (e == i1) ? l[i1] : (e == i2) ? l[i2] : 0.f;
}

// ---------------- launch ----------------
extern "C" void kernel_launch(void* const* d_in, const int* in_sizes, int n_in,
                              void* d_out, int out_size) {
    const float* x        = (const float*)d_in[0];
    const float* mask     = (const float*)d_in[1];
    const float* fcos     = (const float*)d_in[2];
    const float* fsin     = (const float*)d_in[3];
    const float* cache_k  = (const float*)d_in[4];
    const float* cache_v  = (const float*)d_in[5];
    const float* wqkv     = (const float*)d_in[6];
    const float* wo       = (const float*)d_in[7];
    const float* attn_nw  = (const float*)d_in[8];
    const float* ffn_nw   = (const float*)d_in[9];
    const float* ffn_w1   = (const float*)d_in[10];
    const float* ffn_w2   = (const float*)d_in[11];
    const float* ffn_w3   = (const float*)d_in[12];
    const float* gate_w   = (const float*)d_in[13];
    const float* moe_w1   = (const float*)d_in[14];
    const float* moe_w2   = (const float*)d_in[15];
    const float* moe_w3   = (const float*)d_in[16];
    const int*   sp       = (const int*)d_in[17];
    float* out            = (float*)d_out;

    float *an, *qkv, *q, *knew, *vnew, *attn, *h, *fin, *t1, *t3, *gg;
    float *glog, *wexp, *h1, *h3, *ge, *po, *pm, *pl;
    cudaGetSymbolAddress((void**)&an, g_an);
    cudaGetSymbolAddress((void**)&qkv, g_qkv);
    cudaGetSymbolAddress((void**)&q, g_q);
    cudaGetSymbolAddress((void**)&knew, g_knew);
    cudaGetSymbolAddress((void**)&vnew, g_vnew);
    cudaGetSymbolAddress((void**)&attn, g_attn);
    cudaGetSymbolAddress((void**)&h, g_h);
    cudaGetSymbolAddress((void**)&fin, g_fin);
    cudaGetSymbolAddress((void**)&t1, g_t1);
    cudaGetSymbolAddress((void**)&t3, g_t3);
    cudaGetSymbolAddress((void**)&gg, g_g);
    cudaGetSymbolAddress((void**)&glog, g_glog);
    cudaGetSymbolAddress((void**)&wexp, g_wexp);
    cudaGetSymbolAddress((void**)&h1, g_h1);
    cudaGetSymbolAddress((void**)&h3, g_h3);
    cudaGetSymbolAddress((void**)&ge, g_ge);
    cudaGetSymbolAddress((void**)&po, g_part_o);
    cudaGetSymbolAddress((void**)&pm, g_part_m);
    cudaGetSymbolAddress((void**)&pl, g_part_l);

    cudaMemsetAsync(qkv, 0, sizeof(float) * B * QKV_N);
    cudaMemsetAsync(t1, 0, sizeof(float) * B * FD);
    cudaMemsetAsync(t3, 0, sizeof(float) * B * FD);

    // attention
    rmsnorm_kernel<<<B, 1024>>>(x, attn_nw, an);
    gemv_cm4_kernel<<<dim3((QKV_N / 4) / 128, 16), 128>>>(an, wqkv, qkv, DIM, QKV_N, DIM / 16);
    rope_split_kernel<<<B, 512>>>(qkv, fcos, fsin, q, knew, vnew);
    flash_decode_kernel<<<dim3(SPLITS, N_KV, B), 256>>>(q, cache_k, cache_v, knew, vnew,
                                                        mask, sp, po, pm, pl);
    combine_kernel<<<B * NH, HEAD_DIM>>>(po, pm, pl, attn);
    gemv_rm4_kernel<<<DIM / 16, 128>>>(attn, wo, h, DIM, DIM, x);   // h = x + attn@wo.T

    // ffn + moe
    rmsnorm_kernel<<<B, 1024>>>(h, ffn_nw, fin);
    gemv_rm4_kernel<<<1, 128>>>(fin, gate_w, glog, E, DIM, nullptr);
    gate_topk_kernel<<<1, 32>>>(glog, wexp);
    gemv_rm4_dual_atomic_kernel<<<dim3(FD / 16, 2, 2), 128>>>(fin, ffn_w1, ffn_w3, t1, t3, FD, DIM);
    gelumul_kernel<<<(B * FD) / 256, 256>>>(t1, t3, gg, B * FD);
    gemv_rm4_kernel<<<DIM / 16, 128>>>(gg, ffn_w2, out, DIM, FD, h);  // out = h + ff
    moe_up_dual_kernel<<<dim3((E * FE) / 16, 1, 2), 128>>>(fin, moe_w1, moe_w3, h1, h3, wexp);
    gelumul_kernel<<<(B * E * FE) / 256, 256>>>(h1, h3, ge, B * E * FE);
    moe_second4_kernel<<<dim3(DIM / 16, E), 128>>>(ge, moe_w2, wexp, out);  // out += moe
}

// round 14
// speedup vs baseline: 1.3275x; 1.0172x over previous
#include <cuda_runtime.h>
#include <cuda_bf16.h>
#include <math.h>

#define B 8
#define DIM 8192
#define HEAD_DIM 128
#define N_KV 8
#define N_REP 8
#define NH 64
#define KV 4096
#define E 8
#define FD 2048
#define FE 1024
#define QKV_N 10240
#define SPLITS 16
#define JSPL (KV / SPLITS)   /* 256 */
#define JWARP (JSPL / 8)     /* 32  */

// ---------------- scratch ----------------
__device__ float g_an[B * DIM];
__device__ float g_qkv[B * QKV_N];
__device__ float g_q[B * NH * HEAD_DIM];
__device__ float g_knew[B * N_KV * HEAD_DIM];
__device__ float g_vnew[B * N_KV * HEAD_DIM];
__device__ float g_attn[B * DIM];
__device__ float g_h[B * DIM];
__device__ float g_fin[B * DIM];
__device__ float g_t1[B * FD];
__device__ float g_t3[B * FD];
__device__ float g_g[B * FD];
__device__ float g_glog[B * E];
__device__ float g_wexp[B * E];
__device__ float g_h1[B * E * FE];
__device__ float g_h3[B * E * FE];
__device__ float g_ge[B * E * FE];
__device__ float g_part_o[(size_t)B * N_KV * SPLITS * N_REP * HEAD_DIM];
__device__ float g_part_m[B * N_KV * SPLITS * N_REP];
__device__ float g_part_l[B * N_KV * SPLITS * N_REP];

// ---------------- rmsnorm ----------------
__global__ void rmsnorm_kernel(const float* __restrict__ x, const float* __restrict__ w,
                               float* __restrict__ out) {
    int b = blockIdx.x;
    const float* xb = x + (size_t)b * DIM;
    float* ob = out + (size_t)b * DIM;
    float ss = 0.f;
    for (int i = threadIdx.x; i < DIM; i += blockDim.x) {
        float v = xb[i];
        ss += v * v;
    }
    __shared__ float red[32];
    for (int off = 16; off > 0; off >>= 1) ss += __shfl_xor_sync(0xffffffffu, ss, off);
    int lane = threadIdx.x & 31, warp = threadIdx.x >> 5;
    if (lane == 0) red[warp] = ss;
    __syncthreads();
    if (warp == 0) {
        float v = (lane < (int)(blockDim.x >> 5)) ? red[lane] : 0.f;
        for (int off = 16; off > 0; off >>= 1) v += __shfl_xor_sync(0xffffffffu, v, off);
        if (lane == 0) red[0] = v;
    }
    __syncthreads();
    float scale = rsqrtf(red[0] / (float)DIM + 1e-5f);
    for (int i = threadIdx.x; i < DIM; i += blockDim.x)
        ob[i] = xb[i] * scale * w[i];
}

// ---------------- column-major GEMV (x[B,K] @ W[K,N]), k-split + atomics ----------------
__global__ void __launch_bounds__(128, 4)
gemv_cm4_kernel(const float* __restrict__ x, const float* __restrict__ W,
                float* __restrict__ out, int K, int N, int kchunk) {
    int n4 = blockIdx.x * blockDim.x + threadIdx.x;
    int N4 = N >> 2;
    int k0 = blockIdx.y * kchunk;
    __shared__ float xs[B][128];
    float acc[4][B];
#pragma unroll
    for (int r = 0; r < 4; ++r)
#pragma unroll
        for (int b = 0; b < B; ++b) acc[r][b] = 0.f;
    const float4* W4 = (const float4*)W;
    for (int kb = k0; kb < k0 + kchunk; kb += 128) {
        __syncthreads();
        for (int i = threadIdx.x; i < B * 128; i += blockDim.x)
            xs[i >> 7][i & 127] = x[(size_t)(i >> 7) * K + kb + (i & 127)];
        __syncthreads();
#pragma unroll 8
        for (int kk = 0; kk < 128; ++kk) {
            float4 w = __ldcs(W4 + (size_t)(kb + kk) * N4 + n4);
#pragma unroll
            for (int b = 0; b < B; ++b) {
                float xv = xs[b][kk];
                acc[0][b] += w.x * xv;
                acc[1][b] += w.y * xv;
                acc[2][b] += w.z * xv;
                acc[3][b] += w.w * xv;
            }
        }
    }
    int n = n4 * 4;
#pragma unroll
    for (int b = 0; b < B; ++b)
#pragma unroll
        for (int r = 0; r < 4; ++r)
            atomicAdd(&out[(size_t)b * N + n + r], acc[r][b]);
}

// ---------------- proven rm4 GEMV body (R4/R7 loop, weights streamed via __ldcs) ----------------
__device__ __forceinline__ void rm4_body(const float* __restrict__ x,
                                         const float* __restrict__ W,
                                         float* __restrict__ out, int N, int K,
                                         const float* __restrict__ addsrc,
                                         int n0, int lane) {
    int K4 = K >> 2;
    const float4* x4 = (const float4*)x;
    const float4* w0 = (const float4*)(W + (size_t)(n0 + 0) * K);
    const float4* w1 = (const float4*)(W + (size_t)(n0 + 1) * K);
    const float4* w2 = (const float4*)(W + (size_t)(n0 + 2) * K);
    const float4* w3 = (const float4*)(W + (size_t)(n0 + 3) * K);
    float acc[4][B];
#pragma unroll
    for (int r = 0; r < 4; ++r)
#pragma unroll
        for (int b = 0; b < B; ++b) acc[r][b] = 0.f;
#pragma unroll 2
    for (int i = lane; i < K4; i += 32) {
        float4 xv[B];
#pragma unroll
        for (int b = 0; b < B; ++b) xv[b] = x4[(size_t)b * K4 + i];
        float4 w;
        w = __ldcs(w0 + i);
#pragma unroll
        for (int b = 0; b < B; ++b)
            acc[0][b] += w.x * xv[b].x + w.y * xv[b].y + w.z * xv[b].z + w.w * xv[b].w;
        w = __ldcs(w1 + i);
#pragma unroll
        for (int b = 0; b < B; ++b)
            acc[1][b] += w.x * xv[b].x + w.y * xv[b].y + w.z * xv[b].z + w.w * xv[b].w;
        w = __ldcs(w2 + i);
#pragma unroll
        for (int b = 0; b < B; ++b)
            acc[2][b] += w.x * xv[b].x + w.y * xv[b].y + w.z * xv[b].z + w.w * xv[b].w;
        w = __ldcs(w3 + i);
#pragma unroll
        for (int b = 0; b < B; ++b)
            acc[3][b] += w.x * xv[b].x + w.y * xv[b].y + w.z * xv[b].z + w.w * xv[b].w;
    }
#pragma unroll
    for (int r = 0; r < 4; ++r)
#pragma unroll
        for (int b = 0; b < B; ++b)
#pragma unroll
            for (int off = 16; off > 0; off >>= 1)
                acc[r][b] += __shfl_xor_sync(0xffffffffu, acc[r][b], off);
    if (lane == 0) {
#pragma unroll
        for (int r = 0; r < 4; ++r) {
            int n = n0 + r;
            if (n < N) {
#pragma unroll
                for (int b = 0; b < B; ++b) {
                    float v = acc[r][b];
                    if (addsrc) v += addsrc[(size_t)b * N + n];
                    out[(size_t)b * N + n] = v;
                }
            }
        }
    }
}

// direct-store GEMV — 128-thread blocks
__global__ void __launch_bounds__(128, 4)
gemv_rm4_kernel(const float* __restrict__ x, const float* __restrict__ W,
                float* __restrict__ out, int N, int K,
                const float* __restrict__ addsrc) {
    int warp = threadIdx.x >> 5, lane = threadIdx.x & 31;
    int n0 = (blockIdx.x * 4 + warp) * 4;
    if (n0 >= N) return;
    rm4_body(x, W, out, N, K, addsrc, n0, lane);
}

// dual (Wa,Wb via blockIdx.z) + k-split (gridDim.y) atomic; outputs pre-zeroed
__global__ void __launch_bounds__(128, 4)
gemv_rm4_dual_atomic_kernel(const float* __restrict__ x,
                            const float* __restrict__ Wa, const float* __restrict__ Wb,
                            float* __restrict__ outa, float* __restrict__ outb,
                            int N, int K) {
    const float* W = (blockIdx.z == 0) ? Wa : Wb;
    float* out = (blockIdx.z == 0) ? outa : outb;
    int warp = threadIdx.x >> 5, lane = threadIdx.x & 31;
    int n0 = (blockIdx.x * 4 + warp) * 4;
    if (n0 >= N) return;
    int K4 = K >> 2;
    int chunk = K4 / gridDim.y;
    int i0 = blockIdx.y * chunk;
    const float4* x4 = (const float4*)x;
    const float4* w0 = (const float4*)(W + (size_t)(n0 + 0) * K);
    const float4* w1 = (const float4*)(W + (size_t)(n0 + 1) * K);
    const float4* w2 = (const float4*)(W + (size_t)(n0 + 2) * K);
    const float4* w3 = (const float4*)(W + (size_t)(n0 + 3) * K);
    float acc[4][B];
#pragma unroll
    for (int r = 0; r < 4; ++r)
#pragma unroll
        for (int b = 0; b < B; ++b) acc[r][b] = 0.f;
#pragma unroll 2
    for (int i = i0 + lane; i < i0 + chunk; i += 32) {
        float4 xv[B];
#pragma unroll
        for (int b = 0; b < B; ++b) xv[b] = x4[(size_t)b * K4 + i];
        float4 w;
        w = __ldcs(w0 + i);
#pragma unroll
        for (int b = 0; b < B; ++b)
            acc[0][b] += w.x * xv[b].x + w.y * xv[b].y + w.z * xv[b].z + w.w * xv[b].w;
        w = __ldcs(w1 + i);
#pragma unroll
        for (int b = 0; b < B; ++b)
            acc[1][b] += w.x * xv[b].x + w.y * xv[b].y + w.z * xv[b].z + w.w * xv[b].w;
        w = __ldcs(w2 + i);
#pragma unroll
        for (int b = 0; b < B; ++b)
            acc[2][b] += w.x * xv[b].x + w.y * xv[b].y + w.z * xv[b].z + w.w * xv[b].w;
        w = __ldcs(w3 + i);
#pragma unroll
        for (int b = 0; b < B; ++b)
            acc[3][b] += w.x * xv[b].x + w.y * xv[b].y + w.z * xv[b].z + w.w * xv[b].w;
    }
#pragma unroll
    for (int r = 0; r < 4; ++r)
#pragma unroll
        for (int b = 0; b < B; ++b)
#pragma unroll
            for (int off = 16; off > 0; off >>= 1)
                acc[r][b] += __shfl_xor_sync(0xffffffffu, acc[r][b], off);
    if (lane == 0) {
#pragma unroll
        for (int r = 0; r < 4; ++r)
#pragma unroll
            for (int b = 0; b < B; ++b)
                atomicAdd(&out[(size_t)b * N + n0 + r], acc[r][b]);
    }
}

// MoE up: dual (w1,w3), expert skip, direct store — 128-thread blocks
__global__ void __launch_bounds__(128, 4)
moe_up_dual_kernel(const float* __restrict__ x,
                   const float* __restrict__ W1, const float* __restrict__ W3,
                   float* __restrict__ o1, float* __restrict__ o3,
                   const float* __restrict__ wexp) {
    int warp = threadIdx.x >> 5, lane = threadIdx.x & 31;
    int n0 = (blockIdx.x * 4 + warp) * 4;
    int e = n0 >> 10;   // FE = 1024; block's 16 rows stay within one expert
    __shared__ float we[B];
    if (threadIdx.x < B) we[threadIdx.x] = wexp[threadIdx.x * E + e];
    __syncthreads();
    bool any = false;
#pragma unroll
    for (int b = 0; b < B; ++b) any |= (we[b] != 0.f);
    if (!any) return;
    const float* W = (blockIdx.z == 0) ? W1 : W3;
    float* out = (blockIdx.z == 0) ? o1 : o3;
    rm4_body(x, W, out, E * FE, DIM, nullptr, n0, lane);
}

// MoE down-proj, expert skip, weighted atomic — 128-thread blocks
__global__ void __launch_bounds__(128, 4)
moe_second4_kernel(const float* __restrict__ ge, const float* __restrict__ w2,
                   const float* __restrict__ wexp, float* __restrict__ out) {
    int e = blockIdx.y;
    __shared__ float we[B];
    if (threadIdx.x < B) we[threadIdx.x] = wexp[threadIdx.x * E + e];
    __syncthreads();
    bool any = false;
#pragma unroll
    for (int b = 0; b < B; ++b) any |= (we[b] != 0.f);
    if (!any) return;

    int warp = threadIdx.x >> 5, lane = threadIdx.x & 31;
    int n0 = (blockIdx.x * 4 + warp) * 4;
    const float4* x4 = (const float4*)ge;
    int K4 = FE >> 2;
    const float4* w0 = (const float4*)(w2 + ((size_t)e * DIM + n0 + 0) * FE);
    const float4* w1 = (const float4*)(w2 + ((size_t)e * DIM + n0 + 1) * FE);
    const float4* w2p = (const float4*)(w2 + ((size_t)e * DIM + n0 + 2) * FE);
    const float4* w3 = (const float4*)(w2 + ((size_t)e * DIM + n0 + 3) * FE);
    float acc[4][B];
#pragma unroll
    for (int r = 0; r < 4; ++r)
#pragma unroll
        for (int b = 0; b < B; ++b) acc[r][b] = 0.f;
#pragma unroll 2
    for (int i = lane; i < K4; i += 32) {
        float4 xv[B];
#pragma unroll
        for (int b = 0; b < B; ++b) xv[b] = x4[((size_t)b * E + e) * K4 + i];
        float4 w;
        w = __ldcs(w0 + i);
#pragma unroll
        for (int b = 0; b < B; ++b)
            acc[0][b] += w.x * xv[b].x + w.y * xv[b].y + w.z * xv[b].z + w.w * xv[b].w;
        w = __ldcs(w1 + i);
#pragma unroll
        for (int b = 0; b < B; ++b)
            acc[1][b] += w.x * xv[b].x + w.y * xv[b].y + w.z * xv[b].z + w.w * xv[b].w;
        w = __ldcs(w2p + i);
#pragma unroll
        for (int b = 0; b < B; ++b)
            acc[2][b] += w.x * xv[b].x + w.y * xv[b].y + w.z * xv[b].z + w.w * xv[b].w;
        w = __ldcs(w3 + i);
#pragma unroll
        for (int b = 0; b < B; ++b)
            acc[3][b] += w.x * xv[b].x + w.y * xv[b].y + w.z * xv[b].z + w.w * xv[b].w;
    }
#pragma unroll
    for (int r = 0; r < 4; ++r)
#pragma unroll
        for (int b = 0; b < B; ++b)
#pragma unroll
            for (int off = 16; off > 0; off >>= 1)
                acc[r][b] += __shfl_xor_sync(0xffffffffu, acc[r][b], off);
    if (lane == 0) {
#pragma unroll
        for (int r = 0; r < 4; ++r) {
            int n = n0 + r;
#pragma unroll
            for (int b = 0; b < B; ++b)
                if (we[b] != 0.f) atomicAdd(&out[(size_t)b * DIM + n], we[b] * acc[r][b]);
        }
    }
}

// ---------------- rope + split ----------------
__global__ void rope_split_kernel(const float* __restrict__ qkv,
                                  const float* __restrict__ fc, const float* __restrict__ fs,
                                  float* __restrict__ q, float* __restrict__ knew,
                                  float* __restrict__ vnew) {
    int b = blockIdx.x;
    const float* qb = qkv + (size_t)b * QKV_N;
    for (int i = threadIdx.x; i < NH * 64; i += blockDim.x) {
        int h = i >> 6, pi = i & 63;
        int g = h >> 3, r = h & 7;
        const float* base = qb + g * 1280 + r * 128;
        float re = base[2 * pi], im = base[2 * pi + 1];
        float c = fc[pi], s = fs[pi];
        float* qo = q + ((size_t)b * NH + h) * HEAD_DIM;
        qo[2 * pi] = re * c - im * s;
        qo[2 * pi + 1] = re * s + im * c;
    }
    for (int i = threadIdx.x; i < N_KV * 64; i += blockDim.x) {
        int g = i >> 6, pi = i & 63;
        const float* base = qb + g * 1280 + 1024;
        float re = base[2 * pi], im = base[2 * pi + 1];
        float c = fc[pi], s = fs[pi];
        float* ko = knew + ((size_t)b * N_KV + g) * HEAD_DIM;
        ko[2 * pi] = re * c - im * s;
        ko[2 * pi + 1] = re * s + im * c;
    }
    for (int i = threadIdx.x; i < N_KV * HEAD_DIM; i += blockDim.x) {
        int g = i >> 7, d = i & 127;
        vnew[((size_t)b * N_KV + g) * HEAD_DIM + d] = qb[g * 1280 + 1152 + d];
    }
}

// ---------------- fused flash decode (R7 version, known-good) ----------------
__global__ void __launch_bounds__(256, 4)
flash_decode_kernel(const float* __restrict__ q, const float* __restrict__ cache_k,
                    const float* __restrict__ cache_v,
                    const float* __restrict__ knew, const float* __restrict__ vnew,
                    const float* __restrict__ mask, const int* __restrict__ sp_ptr,
                    float* __restrict__ part_o, float* __restrict__ part_m,
                    float* __restrict__ part_l) {
    int split = blockIdx.x, g = blockIdx.y, b = blockIdx.z;
    int sp = *sp_ptr;
    int warp = threadIdx.x >> 5, lane = threadIdx.x & 31;
    int j0 = split * JSPL;

    __shared__ __align__(16) float s[8][JSPL + 4];
    __shared__ float wmax[8][8];

    float4 q4[8];
    const float* qb = q + ((size_t)b * NH + g * 8) * HEAD_DIM;
#pragma unroll
    for (int r = 0; r < 8; ++r)
        q4[r] = ((const float4*)(qb + r * HEAD_DIM))[lane];

    const float scale = 0.08838834764831845f;
    float mloc = -1e30f;

    for (int jj = 0; jj < JWARP; ++jj) {
        int jl = warp * JWARP + jj;
        int j = j0 + jl;
        const float4* krow = (const float4*)((j == sp)
            ? (knew + ((size_t)b * N_KV + g) * HEAD_DIM)
            : (cache_k + (((size_t)b * KV + j) * N_KV + g) * HEAD_DIM));
        float4 k4 = krow[lane];
        float p[8];
#pragma unroll
        for (int r = 0; r < 8; ++r)
            p[r] = k4.x * q4[r].x + k4.y * q4[r].y + k4.z * q4[r].z + k4.w * q4[r].w;
#pragma unroll
        for (int k = 0; k < 4; ++k) {
            float a = p[2 * k], bb = p[2 * k + 1];
            float t = (lane & 1) ? a : bb;
            t = __shfl_xor_sync(0xffffffffu, t, 1);
            p[k] = ((lane & 1) ? bb : a) + t;
        }
#pragma unroll
        for (int k = 0; k < 2; ++k) {
            float a = p[2 * k], bb = p[2 * k + 1];
            float t = (lane & 2) ? a : bb;
            t = __shfl_xor_sync(0xffffffffu, t, 2);
            p[k] = ((lane & 2) ? bb : a) + t;
        }
        {
            float a = p[0], bb = p[1];
            float t = (lane & 4) ? a : bb;
            t = __shfl_xor_sync(0xffffffffu, t, 4);
            p[0] = ((lane & 4) ? bb : a) + t;
        }
        float v = p[0];
        v += __shfl_xor_sync(0xffffffffu, v, 8);
        v += __shfl_xor_sync(0xffffffffu, v, 16);
        if (lane < 8) {
            float sc = v * scale + mask[j];
            s[lane][jl] = sc;
            mloc = fmaxf(mloc, sc);
        }
    }
    if (lane < 8) wmax[warp][lane] = mloc;
    __syncthreads();

    {
        int r = warp;
        float m = wmax[0][r];
#pragma unroll
        for (int w = 1; w < 8; ++w) m = fmaxf(m, wmax[w][r]);
        float ls = 0.f;
        for (int jl = lane; jl < JSPL; jl += 32) {
            float pv = __expf(s[r][jl] - m);
            s[r][jl] = pv;
            ls += pv;
        }
#pragma unroll
        for (int off = 16; off > 0; off >>= 1) ls += __shfl_xor_sync(0xffffffffu, ls, off);
        if (lane == 0) {
            int idx = ((b * N_KV + g) * SPLITS + split) * N_REP + r;
            part_m[idx] = m;
            part_l[idx] = ls;
        }
    }
    __syncthreads();

    float4 acc[8];
#pragma unroll
    for (int r = 0; r < 8; ++r) acc[r] = make_float4(0.f, 0.f, 0.f, 0.f);
    for (int jj = 0; jj < JWARP; ++jj) {
        int jl = warp * JWARP + jj;
        int j = j0 + jl;
        const float4* vrow = (const float4*)((j == sp)
            ? (vnew + ((size_t)b * N_KV + g) * HEAD_DIM)
            : (cache_v + (((size_t)b * KV + j) * N_KV + g) * HEAD_DIM));
        float4 v4 = vrow[lane];
#pragma unroll
        for (int r = 0; r < 8; ++r) {
            float pr = s[r][jl];
            acc[r].x += pr * v4.x;
            acc[r].y += pr * v4.y;
            acc[r].z += pr * v4.z;
            acc[r].w += pr * v4.w;
        }
    }

    float4* sb = (float4*)&s[0][0];
    float* po = part_o + (((size_t)(b * N_KV + g) * SPLITS + split) * N_REP) * HEAD_DIM;
#pragma unroll
    for (int rg = 0; rg < 4; ++rg) {
        __syncthreads();
        sb[(warp * 2 + 0) * 32 + lane] = acc[rg * 2 + 0];
        sb[(warp * 2 + 1) * 32 + lane] = acc[rg * 2 + 1];
        __syncthreads();
        int rrl = threadIdx.x >> 7;
        int d = threadIdx.x & 127;
        float v = 0.f;
        const float* sf = (const float*)sb;
#pragma unroll
        for (int w = 0; w < 8; ++w)
            v += sf[(w * 2 + rrl) * 128 + d];
        po[(rg * 2 + rrl) * HEAD_DIM + d] = v;
    }
}

// ---------------- combine splits ----------------
__global__ void combine_kernel(const float* __restrict__ part_o, const float* __restrict__ part_m,
                               const float* __restrict__ part_l, float* __restrict__ attn) {
    int head = blockIdx.x & 63, b = blockIdx.x >> 6;
    int g = head >> 3, r = head & 7;
    int d = threadIdx.x;
    float M = -1e30f;
#pragma unroll
    for (int sp = 0; sp < SPLITS; ++sp)
        M = fmaxf(M, part_m[((b * N_KV + g) * SPLITS + sp) * N_REP + r]);
    float L = 0.f, acc = 0.f;
#pragma unroll
    for (int sp = 0; sp < SPLITS; ++sp) {
        int idx = ((b * N_KV + g) * SPLITS + sp) * N_REP + r;
        float w = __expf(part_m[idx] - M);
        L += w * part_l[idx];
        acc += w * part_o[(((size_t)(b * N_KV + g) * SPLITS + sp) * N_REP + r) * HEAD_DIM + d];
    }
    attn[((size_t)b * NH + head) * HEAD_DIM + d] = acc / L;
}

// ---------------- gelu(t1)*t3 ----------------
__global__ void gelumul_kernel(const float* __restrict__ t1, const float* __restrict__ t3,
                               float* __restrict__ g, int n) {
    int i = blockIdx.x * blockDim.x + threadIdx.x;
    if (i < n) {
        float x = t1[i];
        g[i] = 0.5f * x * (1.f + erff(x * 0.7071067811865476f)) * t3[i];
    }
}

// ---------------- gate softmax + top-2 ----------------
__global__ void gate_topk_kernel(const float* __restrict__ logits, float* __restrict__ wexp) {
    int b = threadIdx.x;
    if (b >= B) return;
    float l[E];
    float m = -1e30f;
#pragma unroll
    for (int e = 0; e < E; ++e) { l[e] = logits[b * E + e]; m = fmaxf(m, l[e]); }
    float sum = 0.f;
#pragma unroll
    for (int e = 0; e < E; ++e) { l[e] = expf(l[e] - m); sum += l[e]; }
#pragma unroll
    for (int e = 0; e < E; ++e) l[e] /= sum;
    int i1 = 0;
#pragma unroll
    for (int e = 1; e < E; ++e) if (l[e] > l[i1]) i1 = e;
    int i2 = (i1 == 0) ? 1 : 0;
#pragma unroll
    for (int e = 0; e < E; ++e) if (e != i1 && l[e] > l[i2]) i2 = e;
#pragma unroll
    for (int e = 0; e < E; ++e)
        wexp[b * E + e] = (e == i1) ? l[i1] : (e == i2) ? l[i2] : 0.f;
}

// ---------------- launch ----------------
extern "C" void kernel_launch(void* const* d_in, const int* in_sizes, int n_in,
                              void* d_out, int out_size) {
    const float* x        = (const float*)d_in[0];
    const float* mask     = (const float*)d_in[1];
    const float* fcos     = (const float*)d_in[2];
    const float* fsin     = (const float*)d_in[3];
    const float* cache_k  = (const float*)d_in[4];
    const float* cache_v  = (const float*)d_in[5];
    const float* wqkv     = (const float*)d_in[6];
    const float* wo       = (const float*)d_in[7];
    const float* attn_nw  = (const float*)d_in[8];
    const float* ffn_nw   = (const float*)d_in[9];
    const float* ffn_w1   = (const float*)d_in[10];
    const float* ffn_w2   = (const float*)d_in[11];
    const float* ffn_w3   = (const float*)d_in[12];
    const float* gate_w   = (const float*)d_in[13];
    const float* moe_w1   = (const float*)d_in[14];
    const float* moe_w2   = (const float*)d_in[15];
    const float* moe_w3   = (const float*)d_in[16];
    const int*   sp       = (const int*)d_in[17];
    float* out            = (float*)d_out;

    float *an, *qkv, *q, *knew, *vnew, *attn, *h, *fin, *t1, *t3, *gg;
    float *glog, *wexp, *h1, *h3, *ge, *po, *pm, *pl;
    cudaGetSymbolAddress((void**)&an, g_an);
    cudaGetSymbolAddress((void**)&qkv, g_qkv);
    cudaGetSymbolAddress((void**)&q, g_q);
    cudaGetSymbolAddress((void**)&knew, g_knew);
    cudaGetSymbolAddress((void**)&vnew, g_vnew);
    cudaGetSymbolAddress((void**)&attn, g_attn);
    cudaGetSymbolAddress((void**)&h, g_h);
    cudaGetSymbolAddress((void**)&fin, g_fin);
    cudaGetSymbolAddress((void**)&t1, g_t1);
    cudaGetSymbolAddress((void**)&t3, g_t3);
    cudaGetSymbolAddress((void**)&gg, g_g);
    cudaGetSymbolAddress((void**)&glog, g_glog);
    cudaGetSymbolAddress((void**)&wexp, g_wexp);
    cudaGetSymbolAddress((void**)&h1, g_h1);
    cudaGetSymbolAddress((void**)&h3, g_h3);
    cudaGetSymbolAddress((void**)&ge, g_ge);
    cudaGetSymbolAddress((void**)&po, g_part_o);
    cudaGetSymbolAddress((void**)&pm, g_part_m);
    cudaGetSymbolAddress((void**)&pl, g_part_l);

    cudaMemsetAsync(qkv, 0, sizeof(float) * B * QKV_N);
    cudaMemsetAsync(t1, 0, sizeof(float) * B * FD);
    cudaMemsetAsync(t3, 0, sizeof(float) * B * FD);

    // attention
    rmsnorm_kernel<<<B, 1024>>>(x, attn_nw, an);
    gemv_cm4_kernel<<<dim3((QKV_N / 4) / 128, 16), 128>>>(an, wqkv, qkv, DIM, QKV_N, DIM / 16);
    rope_split_kernel<<<B, 512>>>(qkv, fcos, fsin, q, knew, vnew);
    flash_decode_kernel<<<dim3(SPLITS, N_KV, B), 256>>>(q, cache_k, cache_v, knew, vnew,
                                                        mask, sp, po, pm, pl);
    combine_kernel<<<B * NH, HEAD_DIM>>>(po, pm, pl, attn);
    gemv_rm4_kernel<<<DIM / 16, 128>>>(attn, wo, h, DIM, DIM, x);   // h = x + attn@wo.T

    // ffn + moe
    rmsnorm_kernel<<<B, 1024>>>(h, ffn_nw, fin);
    gemv_rm4_kernel<<<1, 128>>>(fin, gate_w, glog, E, DIM, nullptr);
    gate_topk_kernel<<<1, 32>>>(glog, wexp);
    gemv_rm4_dual_atomic_kernel<<<dim3(FD / 16, 2, 2), 128>>>(fin, ffn_w1, ffn_w3, t1, t3, FD, DIM);
    gelumul_kernel<<<(B * FD) / 256, 256>>>(t1, t3, gg, B * FD);
    gemv_rm4_kernel<<<DIM / 16, 128>>>(gg, ffn_w2, out, DIM, FD, h);  // out = h + ff
    moe_up_dual_kernel<<<dim3((E * FE) / 16, 1, 2), 128>>>(fin, moe_w1, moe_w3, h1, h3, wexp);
    gelumul_kernel<<<(B * E * FE) / 256, 256>>>(h1, h3, ge, B * E * FE);
    moe_second4_kernel<<<dim3(DIM / 16, E), 128>>>(ge, moe_w2, wexp, out);  // out += moe
}

// round 16
// speedup vs baseline: 1.3386x; 1.0084x over previous
#include <cuda_runtime.h>
#include <cuda_bf16.h>
#include <math.h>

#define B 8
#define DIM 8192
#define HEAD_DIM 128
#define N_KV 8
#define N_REP 8
#define NH 64
#define KV 4096
#define E 8
#define FD 2048
#define FE 1024
#define QKV_N 10240
#define SPLITS 16
#define JSPL (KV / SPLITS)   /* 256 */
#define JWARP (JSPL / 8)     /* 32  */

// ---------------- scratch ----------------
__device__ float g_an[B * DIM];
__device__ float g_qkv[B * QKV_N];
__device__ float g_q[B * NH * HEAD_DIM];
__device__ float g_knew[B * N_KV * HEAD_DIM];
__device__ float g_vnew[B * N_KV * HEAD_DIM];
__device__ float g_attn[B * DIM];
__device__ float g_h[B * DIM];
__device__ float g_fin[B * DIM];
__device__ float g_t1[B * FD];
__device__ float g_t3[B * FD];
__device__ float g_g[B * FD];
__device__ float g_glog[B * E];
__device__ float g_wexp[B * E];
__device__ float g_h1[B * E * FE];
__device__ float g_h3[B * E * FE];
__device__ float g_ge[B * E * FE];
__device__ float g_part_o[(size_t)B * N_KV * SPLITS * N_REP * HEAD_DIM];
__device__ float g_part_m[B * N_KV * SPLITS * N_REP];
__device__ float g_part_l[B * N_KV * SPLITS * N_REP];

// ---------------- rmsnorm ----------------
__global__ void rmsnorm_kernel(const float* __restrict__ x, const float* __restrict__ w,
                               float* __restrict__ out) {
    int b = blockIdx.x;
    const float* xb = x + (size_t)b * DIM;
    float* ob = out + (size_t)b * DIM;
    float ss = 0.f;
    for (int i = threadIdx.x; i < DIM; i += blockDim.x) {
        float v = xb[i];
        ss += v * v;
    }
    __shared__ float red[32];
    for (int off = 16; off > 0; off >>= 1) ss += __shfl_xor_sync(0xffffffffu, ss, off);
    int lane = threadIdx.x & 31, warp = threadIdx.x >> 5;
    if (lane == 0) red[warp] = ss;
    __syncthreads();
    if (warp == 0) {
        float v = (lane < (int)(blockDim.x >> 5)) ? red[lane] : 0.f;
        for (int off = 16; off > 0; off >>= 1) v += __shfl_xor_sync(0xffffffffu, v, off);
        if (lane == 0) red[0] = v;
    }
    __syncthreads();
    float scale = rsqrtf(red[0] / (float)DIM + 1e-5f);
    for (int i = threadIdx.x; i < DIM; i += blockDim.x)
        ob[i] = xb[i] * scale * w[i];
}

// ---------------- column-major GEMV (x[B,K] @ W[K,N]), k-split + atomics ----------------
__global__ void __launch_bounds__(128, 4)
gemv_cm4_kernel(const float* __restrict__ x, const float* __restrict__ W,
                float* __restrict__ out, int K, int N, int kchunk) {
    int n4 = blockIdx.x * blockDim.x + threadIdx.x;
    int N4 = N >> 2;
    int k0 = blockIdx.y * kchunk;
    __shared__ float xs[B][128];
    float acc[4][B];
#pragma unroll
    for (int r = 0; r < 4; ++r)
#pragma unroll
        for (int b = 0; b < B; ++b) acc[r][b] = 0.f;
    const float4* W4 = (const float4*)W;
    for (int kb = k0; kb < k0 + kchunk; kb += 128) {
        __syncthreads();
        for (int i = threadIdx.x; i < B * 128; i += blockDim.x)
            xs[i >> 7][i & 127] = x[(size_t)(i >> 7) * K + kb + (i & 127)];
        __syncthreads();
#pragma unroll 8
        for (int kk = 0; kk < 128; ++kk) {
            float4 w = __ldcs(W4 + (size_t)(kb + kk) * N4 + n4);
#pragma unroll
            for (int b = 0; b < B; ++b) {
                float xv = xs[b][kk];
                acc[0][b] += w.x * xv;
                acc[1][b] += w.y * xv;
                acc[2][b] += w.z * xv;
                acc[3][b] += w.w * xv;
            }
        }
    }
    int n = n4 * 4;
#pragma unroll
    for (int b = 0; b < B; ++b)
#pragma unroll
        for (int r = 0; r < 4; ++r)
            atomicAdd(&out[(size_t)b * N + n + r], acc[r][b]);
}

// ---------------- proven rm4 GEMV body (weights streamed via __ldcs) ----------------
__device__ __forceinline__ void rm4_body(const float* __restrict__ x,
                                         const float* __restrict__ W,
                                         float* __restrict__ out, int N, int K,
                                         const float* __restrict__ addsrc,
                                         int n0, int lane) {
    int K4 = K >> 2;
    const float4* x4 = (const float4*)x;
    const float4* w0 = (const float4*)(W + (size_t)(n0 + 0) * K);
    const float4* w1 = (const float4*)(W + (size_t)(n0 + 1) * K);
    const float4* w2 = (const float4*)(W + (size_t)(n0 + 2) * K);
    const float4* w3 = (const float4*)(W + (size_t)(n0 + 3) * K);
    float acc[4][B];
#pragma unroll
    for (int r = 0; r < 4; ++r)
#pragma unroll
        for (int b = 0; b < B; ++b) acc[r][b] = 0.f;
#pragma unroll 2
    for (int i = lane; i < K4; i += 32) {
        float4 xv[B];
#pragma unroll
        for (int b = 0; b < B; ++b) xv[b] = x4[(size_t)b * K4 + i];
        float4 w;
        w = __ldcs(w0 + i);
#pragma unroll
        for (int b = 0; b < B; ++b)
            acc[0][b] += w.x * xv[b].x + w.y * xv[b].y + w.z * xv[b].z + w.w * xv[b].w;
        w = __ldcs(w1 + i);
#pragma unroll
        for (int b = 0; b < B; ++b)
            acc[1][b] += w.x * xv[b].x + w.y * xv[b].y + w.z * xv[b].z + w.w * xv[b].w;
        w = __ldcs(w2 + i);
#pragma unroll
        for (int b = 0; b < B; ++b)
            acc[2][b] += w.x * xv[b].x + w.y * xv[b].y + w.z * xv[b].z + w.w * xv[b].w;
        w = __ldcs(w3 + i);
#pragma unroll
        for (int b = 0; b < B; ++b)
            acc[3][b] += w.x * xv[b].x + w.y * xv[b].y + w.z * xv[b].z + w.w * xv[b].w;
    }
#pragma unroll
    for (int r = 0; r < 4; ++r)
#pragma unroll
        for (int b = 0; b < B; ++b)
#pragma unroll
            for (int off = 16; off > 0; off >>= 1)
                acc[r][b] += __shfl_xor_sync(0xffffffffu, acc[r][b], off);
    if (lane == 0) {
#pragma unroll
        for (int r = 0; r < 4; ++r) {
            int n = n0 + r;
            if (n < N) {
#pragma unroll
                for (int b = 0; b < B; ++b) {
                    float v = acc[r][b];
                    if (addsrc) v += addsrc[(size_t)b * N + n];
                    out[(size_t)b * N + n] = v;
                }
            }
        }
    }
}

// direct-store GEMV — 128-thread blocks
__global__ void __launch_bounds__(128, 4)
gemv_rm4_kernel(const float* __restrict__ x, const float* __restrict__ W,
                float* __restrict__ out, int N, int K,
                const float* __restrict__ addsrc) {
    int warp = threadIdx.x >> 5, lane = threadIdx.x & 31;
    int n0 = (blockIdx.x * 4 + warp) * 4;
    if (n0 >= N) return;
    rm4_body(x, W, out, N, K, addsrc, n0, lane);
}

// dual (Wa,Wb via blockIdx.z) + k-split (gridDim.y) atomic; outputs pre-zeroed
__global__ void __launch_bounds__(128, 4)
gemv_rm4_dual_atomic_kernel(const float* __restrict__ x,
                            const float* __restrict__ Wa, const float* __restrict__ Wb,
                            float* __restrict__ outa, float* __restrict__ outb,
                            int N, int K) {
    const float* W = (blockIdx.z == 0) ? Wa : Wb;
    float* out = (blockIdx.z == 0) ? outa : outb;
    int warp = threadIdx.x >> 5, lane = threadIdx.x & 31;
    int n0 = (blockIdx.x * 4 + warp) * 4;
    if (n0 >= N) return;
    int K4 = K >> 2;
    int chunk = K4 / gridDim.y;
    int i0 = blockIdx.y * chunk;
    const float4* x4 = (const float4*)x;
    const float4* w0 = (const float4*)(W + (size_t)(n0 + 0) * K);
    const float4* w1 = (const float4*)(W + (size_t)(n0 + 1) * K);
    const float4* w2 = (const float4*)(W + (size_t)(n0 + 2) * K);
    const float4* w3 = (const float4*)(W + (size_t)(n0 + 3) * K);
    float acc[4][B];
#pragma unroll
    for (int r = 0; r < 4; ++r)
#pragma unroll
        for (int b = 0; b < B; ++b) acc[r][b] = 0.f;
#pragma unroll 2
    for (int i = i0 + lane; i < i0 + chunk; i += 32) {
        float4 xv[B];
#pragma unroll
        for (int b = 0; b < B; ++b) xv[b] = x4[(size_t)b * K4 + i];
        float4 w;
        w = __ldcs(w0 + i);
#pragma unroll
        for (int b = 0; b < B; ++b)
            acc[0][b] += w.x * xv[b].x + w.y * xv[b].y + w.z * xv[b].z + w.w * xv[b].w;
        w = __ldcs(w1 + i);
#pragma unroll
        for (int b = 0; b < B; ++b)
            acc[1][b] += w.x * xv[b].x + w.y * xv[b].y + w.z * xv[b].z + w.w * xv[b].w;
        w = __ldcs(w2 + i);
#pragma unroll
        for (int b = 0; b < B; ++b)
            acc[2][b] += w.x * xv[b].x + w.y * xv[b].y + w.z * xv[b].z + w.w * xv[b].w;
        w = __ldcs(w3 + i);
#pragma unroll
        for (int b = 0; b < B; ++b)
            acc[3][b] += w.x * xv[b].x + w.y * xv[b].y + w.z * xv[b].z + w.w * xv[b].w;
    }
#pragma unroll
    for (int r = 0; r < 4; ++r)
#pragma unroll
        for (int b = 0; b < B; ++b)
#pragma unroll
            for (int off = 16; off > 0; off >>= 1)
                acc[r][b] += __shfl_xor_sync(0xffffffffu, acc[r][b], off);
    if (lane == 0) {
#pragma unroll
        for (int r = 0; r < 4; ++r)
#pragma unroll
            for (int b = 0; b < B; ++b)
                atomicAdd(&out[(size_t)b * N + n0 + r], acc[r][b]);
    }
}

// MoE up: dual (w1,w3), expert skip, direct store — 128-thread blocks
__global__ void __launch_bounds__(128, 4)
moe_up_dual_kernel(const float* __restrict__ x,
                   const float* __restrict__ W1, const float* __restrict__ W3,
                   float* __restrict__ o1, float* __restrict__ o3,
                   const float* __restrict__ wexp) {
    int warp = threadIdx.x >> 5, lane = threadIdx.x & 31;
    int n0 = (blockIdx.x * 4 + warp) * 4;
    int e = n0 >> 10;   // FE = 1024; block's 16 rows stay within one expert
    __shared__ float we[B];
    if (threadIdx.x < B) we[threadIdx.x] = wexp[threadIdx.x * E + e];
    __syncthreads();
    bool any = false;
#pragma unroll
    for (int b = 0; b < B; ++b) any |= (we[b] != 0.f);
    if (!any) return;
    const float* W = (blockIdx.z == 0) ? W1 : W3;
    float* out = (blockIdx.z == 0) ? o1 : o3;
    rm4_body(x, W, out, E * FE, DIM, nullptr, n0, lane);
}

// MoE down-proj, expert skip, weighted atomic — 128-thread blocks
__global__ void __launch_bounds__(128, 4)
moe_second4_kernel(const float* __restrict__ ge, const float* __restrict__ w2,
                   const float* __restrict__ wexp, float* __restrict__ out) {
    int e = blockIdx.y;
    __shared__ float we[B];
    if (threadIdx.x < B) we[threadIdx.x] = wexp[threadIdx.x * E + e];
    __syncthreads();
    bool any = false;
#pragma unroll
    for (int b = 0; b < B; ++b) any |= (we[b] != 0.f);
    if (!any) return;

    int warp = threadIdx.x >> 5, lane = threadIdx.x & 31;
    int n0 = (blockIdx.x * 4 + warp) * 4;
    const float4* x4 = (const float4*)ge;
    int K4 = FE >> 2;
    const float4* w0 = (const float4*)(w2 + ((size_t)e * DIM + n0 + 0) * FE);
    const float4* w1 = (const float4*)(w2 + ((size_t)e * DIM + n0 + 1) * FE);
    const float4* w2p = (const float4*)(w2 + ((size_t)e * DIM + n0 + 2) * FE);
    const float4* w3 = (const float4*)(w2 + ((size_t)e * DIM + n0 + 3) * FE);
    float acc[4][B];
#pragma unroll
    for (int r = 0; r < 4; ++r)
#pragma unroll
        for (int b = 0; b < B; ++b) acc[r][b] = 0.f;
#pragma unroll 2
    for (int i = lane; i < K4; i += 32) {
        float4 xv[B];
#pragma unroll
        for (int b = 0; b < B; ++b) xv[b] = x4[((size_t)b * E + e) * K4 + i];
        float4 w;
        w = __ldcs(w0 + i);
#pragma unroll
        for (int b = 0; b < B; ++b)
            acc[0][b] += w.x * xv[b].x + w.y * xv[b].y + w.z * xv[b].z + w.w * xv[b].w;
        w = __ldcs(w1 + i);
#pragma unroll
        for (int b = 0; b < B; ++b)
            acc[1][b] += w.x * xv[b].x + w.y * xv[b].y + w.z * xv[b].z + w.w * xv[b].w;
        w = __ldcs(w2p + i);
#pragma unroll
        for (int b = 0; b < B; ++b)
            acc[2][b] += w.x * xv[b].x + w.y * xv[b].y + w.z * xv[b].z + w.w * xv[b].w;
        w = __ldcs(w3 + i);
#pragma unroll
        for (int b = 0; b < B; ++b)
            acc[3][b] += w.x * xv[b].x + w.y * xv[b].y + w.z * xv[b].z + w.w * xv[b].w;
    }
#pragma unroll
    for (int r = 0; r < 4; ++r)
#pragma unroll
        for (int b = 0; b < B; ++b)
#pragma unroll
            for (int off = 16; off > 0; off >>= 1)
                acc[r][b] += __shfl_xor_sync(0xffffffffu, acc[r][b], off);
    if (lane == 0) {
#pragma unroll
        for (int r = 0; r < 4; ++r) {
            int n = n0 + r;
#pragma unroll
            for (int b = 0; b < B; ++b)
                if (we[b] != 0.f) atomicAdd(&out[(size_t)b * DIM + n], we[b] * acc[r][b]);
        }
    }
}

// ---------------- rope + split ----------------
__global__ void rope_split_kernel(const float* __restrict__ qkv,
                                  const float* __restrict__ fc, const float* __restrict__ fs,
                                  float* __restrict__ q, float* __restrict__ knew,
                                  float* __restrict__ vnew) {
    int b = blockIdx.x;
    const float* qb = qkv + (size_t)b * QKV_N;
    for (int i = threadIdx.x; i < NH * 64; i += blockDim.x) {
        int h = i >> 6, pi = i & 63;
        int g = h >> 3, r = h & 7;
        const float* base = qb + g * 1280 + r * 128;
        float re = base[2 * pi], im = base[2 * pi + 1];
        float c = fc[pi], s = fs[pi];
        float* qo = q + ((size_t)b * NH + h) * HEAD_DIM;
        qo[2 * pi] = re * c - im * s;
        qo[2 * pi + 1] = re * s + im * c;
    }
    for (int i = threadIdx.x; i < N_KV * 64; i += blockDim.x) {
        int g = i >> 6, pi = i & 63;
        const float* base = qb + g * 1280 + 1024;
        float re = base[2 * pi], im = base[2 * pi + 1];
        float c = fc[pi], s = fs[pi];
        float* ko = knew + ((size_t)b * N_KV + g) * HEAD_DIM;
        ko[2 * pi] = re * c - im * s;
        ko[2 * pi + 1] = re * s + im * c;
    }
    for (int i = threadIdx.x; i < N_KV * HEAD_DIM; i += blockDim.x) {
        int g = i >> 7, d = i & 127;
        vnew[((size_t)b * N_KV + g) * HEAD_DIM + d] = qb[g * 1280 + 1152 + d];
    }
}

// ---------------- fused flash decode (R7 structure; KV streamed via __ldcs) ----------------
__global__ void __launch_bounds__(256, 4)
flash_decode_kernel(const float* __restrict__ q, const float* __restrict__ cache_k,
                    const float* __restrict__ cache_v,
                    const float* __restrict__ knew, const float* __restrict__ vnew,
                    const float* __restrict__ mask, const int* __restrict__ sp_ptr,
                    float* __restrict__ part_o, float* __restrict__ part_m,
                    float* __restrict__ part_l) {
    int split = blockIdx.x, g = blockIdx.y, b = blockIdx.z;
    int sp = *sp_ptr;
    int warp = threadIdx.x >> 5, lane = threadIdx.x & 31;
    int j0 = split * JSPL;

    __shared__ __align__(16) float s[8][JSPL + 4];
    __shared__ float wmax[8][8];

    float4 q4[8];
    const float* qb = q + ((size_t)b * NH + g * 8) * HEAD_DIM;
#pragma unroll
    for (int r = 0; r < 8; ++r)
        q4[r] = ((const float4*)(qb + r * HEAD_DIM))[lane];

    const float scale = 0.08838834764831845f;
    float mloc = -1e30f;

    for (int jj = 0; jj < JWARP; ++jj) {
        int jl = warp * JWARP + jj;
        int j = j0 + jl;
        const float4* krow = (const float4*)((j == sp)
            ? (knew + ((size_t)b * N_KV + g) * HEAD_DIM)
            : (cache_k + (((size_t)b * KV + j) * N_KV + g) * HEAD_DIM));
        float4 k4 = __ldcs(krow + lane);
        float p[8];
#pragma unroll
        for (int r = 0; r < 8; ++r)
            p[r] = k4.x * q4[r].x + k4.y * q4[r].y + k4.z * q4[r].z + k4.w * q4[r].w;
#pragma unroll
        for (int k = 0; k < 4; ++k) {
            float a = p[2 * k], bb = p[2 * k + 1];
            float t = (lane & 1) ? a : bb;
            t = __shfl_xor_sync(0xffffffffu, t, 1);
            p[k] = ((lane & 1) ? bb : a) + t;
        }
#pragma unroll
        for (int k = 0; k < 2; ++k) {
            float a = p[2 * k], bb = p[2 * k + 1];
            float t = (lane & 2) ? a : bb;
            t = __shfl_xor_sync(0xffffffffu, t, 2);
            p[k] = ((lane & 2) ? bb : a) + t;
        }
        {
            float a = p[0], bb = p[1];
            float t = (lane & 4) ? a : bb;
            t = __shfl_xor_sync(0xffffffffu, t, 4);
            p[0] = ((lane & 4) ? bb : a) + t;
        }
        float v = p[0];
        v += __shfl_xor_sync(0xffffffffu, v, 8);
        v += __shfl_xor_sync(0xffffffffu, v, 16);
        if (lane < 8) {
            float sc = v * scale + mask[j];
            s[lane][jl] = sc;
            mloc = fmaxf(mloc, sc);
        }
    }
    if (lane < 8) wmax[warp][lane] = mloc;
    __syncthreads();

    {
        int r = warp;
        float m = wmax[0][r];
#pragma unroll
        for (int w = 1; w < 8; ++w) m = fmaxf(m, wmax[w][r]);
        float ls = 0.f;
        for (int jl = lane; jl < JSPL; jl += 32) {
            float pv = __expf(s[r][jl] - m);
            s[r][jl] = pv;
            ls += pv;
        }
#pragma unroll
        for (int off = 16; off > 0; off >>= 1) ls += __shfl_xor_sync(0xffffffffu, ls, off);
        if (lane == 0) {
            int idx = ((b * N_KV + g) * SPLITS + split) * N_REP + r;
            part_m[idx] = m;
            part_l[idx] = ls;
        }
    }
    __syncthreads();

    float4 acc[8];
#pragma unroll
    for (int r = 0; r < 8; ++r) acc[r] = make_float4(0.f, 0.f, 0.f, 0.f);
    for (int jj = 0; jj < JWARP; ++jj) {
        int jl = warp * JWARP + jj;
        int j = j0 + jl;
        const float4* vrow = (const float4*)((j == sp)
            ? (vnew + ((size_t)b * N_KV + g) * HEAD_DIM)
            : (cache_v + (((size_t)b * KV + j) * N_KV + g) * HEAD_DIM));
        float4 v4 = __ldcs(vrow + lane);
#pragma unroll
        for (int r = 0; r < 8; ++r) {
            float pr = s[r][jl];
            acc[r].x += pr * v4.x;
            acc[r].y += pr * v4.y;
            acc[r].z += pr * v4.z;
            acc[r].w += pr * v4.w;
        }
    }

    float4* sb = (float4*)&s[0][0];
    float* po = part_o + (((size_t)(b * N_KV + g) * SPLITS + split) * N_REP) * HEAD_DIM;
#pragma unroll
    for (int rg = 0; rg < 4; ++rg) {
        __syncthreads();
        sb[(warp * 2 + 0) * 32 + lane] = acc[rg * 2 + 0];
        sb[(warp * 2 + 1) * 32 + lane] = acc[rg * 2 + 1];
        __syncthreads();
        int rrl = threadIdx.x >> 7;
        int d = threadIdx.x & 127;
        float v = 0.f;
        const float* sf = (const float*)sb;
#pragma unroll
        for (int w = 0; w < 8; ++w)
            v += sf[(w * 2 + rrl) * 128 + d];
        po[(rg * 2 + rrl) * HEAD_DIM + d] = v;
    }
}

// ---------------- combine splits (part_o streamed) ----------------
__global__ void combine_kernel(const float* __restrict__ part_o, const float* __restrict__ part_m,
                               const float* __restrict__ part_l, float* __restrict__ attn) {
    int head = blockIdx.x & 63, b = blockIdx.x >> 6;
    int g = head >> 3, r = head & 7;
    int d = threadIdx.x;
    float M = -1e30f;
#pragma unroll
    for (int sp = 0; sp < SPLITS; ++sp)
        M = fmaxf(M, part_m[((b * N_KV + g) * SPLITS + sp) * N_REP + r]);
    float L = 0.f, acc = 0.f;
#pragma unroll
    for (int sp = 0; sp < SPLITS; ++sp) {
        int idx = ((b * N_KV + g) * SPLITS + sp) * N_REP + r;
        float w = __expf(part_m[idx] - M);
        L += w * part_l[idx];
        acc += w * __ldcs(part_o + (((size_t)(b * N_KV + g) * SPLITS + sp) * N_REP + r) * HEAD_DIM + d);
    }
    attn[((size_t)b * NH + head) * HEAD_DIM + d] = acc / L;
}

// ---------------- gelu(t1)*t3 ----------------
__global__ void gelumul_kernel(const float* __restrict__ t1, const float* __restrict__ t3,
                               float* __restrict__ g, int n) {
    int i = blockIdx.x * blockDim.x + threadIdx.x;
    if (i < n) {
        float x = __ldcs(t1 + i);
        g[i] = 0.5f * x * (1.f + erff(x * 0.7071067811865476f)) * __ldcs(t3 + i);
    }
}

// ---------------- gate softmax + top-2 ----------------
__global__ void gate_topk_kernel(const float* __restrict__ logits, float* __restrict__ wexp) {
    int b = threadIdx.x;
    if (b >= B) return;
    float l[E];
    float m = -1e30f;
#pragma unroll
    for (int e = 0; e < E; ++e) { l[e] = logits[b * E + e]; m = fmaxf(m, l[e]); }
    float sum = 0.f;
#pragma unroll
    for (int e = 0; e < E; ++e) { l[e] = expf(l[e] - m); sum += l[e]; }
#pragma unroll
    for (int e = 0; e < E; ++e) l[e] /= sum;
    int i1 = 0;
#pragma unroll
    for (int e = 1; e < E; ++e) if (l[e] > l[i1]) i1 = e;
    int i2 = (i1 == 0) ? 1 : 0;
#pragma unroll
    for (int e = 0; e < E; ++e) if (e != i1 && l[e] > l[i2]) i2 = e;
#pragma unroll
    for (int e = 0; e < E; ++e)
        wexp[b * E + e] = (e == i1) ? l[i1] : (e == i2) ? l[i2] : 0.f;
}

// ---------------- launch ----------------
extern "C" void kernel_launch(void* const* d_in, const int* in_sizes, int n_in,
                              void* d_out, int out_size) {
    const float* x        = (const float*)d_in[0];
    const float* mask     = (const float*)d_in[1];
    const float* fcos     = (const float*)d_in[2];
    const float* fsin     = (const float*)d_in[3];
    const float* cache_k  = (const float*)d_in[4];
    const float* cache_v  = (const float*)d_in[5];
    const float* wqkv     = (const float*)d_in[6];
    const float* wo       = (const float*)d_in[7];
    const float* attn_nw  = (const float*)d_in[8];
    const float* ffn_nw   = (const float*)d_in[9];
    const float* ffn_w1   = (const float*)d_in[10];
    const float* ffn_w2   = (const float*)d_in[11];
    const float* ffn_w3   = (const float*)d_in[12];
    const float* gate_w   = (const float*)d_in[13];
    const float* moe_w1   = (const float*)d_in[14];
    const float* moe_w2   = (const float*)d_in[15];
    const float* moe_w3   = (const float*)d_in[16];
    const int*   sp       = (const int*)d_in[17];
    float* out            = (float*)d_out;

    float *an, *qkv, *q, *knew, *vnew, *attn, *h, *fin, *t1, *t3, *gg;
    float *glog, *wexp, *h1, *h3, *ge, *po, *pm, *pl;
    cudaGetSymbolAddress((void**)&an, g_an);
    cudaGetSymbolAddress((void**)&qkv, g_qkv);
    cudaGetSymbolAddress((void**)&q, g_q);
    cudaGetSymbolAddress((void**)&knew, g_knew);
    cudaGetSymbolAddress((void**)&vnew, g_vnew);
    cudaGetSymbolAddress((void**)&attn, g_attn);
    cudaGetSymbolAddress((void**)&h, g_h);
    cudaGetSymbolAddress((void**)&fin, g_fin);
    cudaGetSymbolAddress((void**)&t1, g_t1);
    cudaGetSymbolAddress((void**)&t3, g_t3);
    cudaGetSymbolAddress((void**)&gg, g_g);
    cudaGetSymbolAddress((void**)&glog, g_glog);
    cudaGetSymbolAddress((void**)&wexp, g_wexp);
    cudaGetSymbolAddress((void**)&h1, g_h1);
    cudaGetSymbolAddress((void**)&h3, g_h3);
    cudaGetSymbolAddress((void**)&ge, g_ge);
    cudaGetSymbolAddress((void**)&po, g_part_o);
    cudaGetSymbolAddress((void**)&pm, g_part_m);
    cudaGetSymbolAddress((void**)&pl, g_part_l);

    cudaMemsetAsync(qkv, 0, sizeof(float) * B * QKV_N);
    cudaMemsetAsync(t1, 0, sizeof(float) * B * FD);
    cudaMemsetAsync(t3, 0, sizeof(float) * B * FD);

    // attention
    rmsnorm_kernel<<<B, 1024>>>(x, attn_nw, an);
    gemv_cm4_kernel<<<dim3((QKV_N / 4) / 128, 16), 128>>>(an, wqkv, qkv, DIM, QKV_N, DIM / 16);
    rope_split_kernel<<<B, 512>>>(qkv, fcos, fsin, q, knew, vnew);
    flash_decode_kernel<<<dim3(SPLITS, N_KV, B), 256>>>(q, cache_k, cache_v, knew, vnew,
                                                        mask, sp, po, pm, pl);
    combine_kernel<<<B * NH, HEAD_DIM>>>(po, pm, pl, attn);
    gemv_rm4_kernel<<<DIM / 16, 128>>>(attn, wo, h, DIM, DIM, x);   // h = x + attn@wo.T

    // ffn + moe
    rmsnorm_kernel<<<B, 1024>>>(h, ffn_nw, fin);
    gemv_rm4_kernel<<<1, 128>>>(fin, gate_w, glog, E, DIM, nullptr);
    gate_topk_kernel<<<1, 32>>>(glog, wexp);
    gemv_rm4_dual_atomic_kernel<<<dim3(FD / 16, 2, 2), 128>>>(fin, ffn_w1, ffn_w3, t1, t3, FD, DIM);
    gelumul_kernel<<<(B * FD) / 256, 256>>>(t1, t3, gg, B * FD);
    gemv_rm4_kernel<<<DIM / 16, 128>>>(gg, ffn_w2, out, DIM, FD, h);  // out = h + ff
    moe_up_dual_kernel<<<dim3((E * FE) / 16, 1, 2), 128>>>(fin, moe_w1, moe_w3, h1, h3, wexp);
    gelumul_kernel<<<(B * E * FE) / 256, 256>>>(h1, h3, ge, B * E * FE);
    moe_second4_kernel<<<dim3(DIM / 16, E), 128>>>(ge, moe_w2, wexp, out);  // out += moe
}

// round 17
// speedup vs baseline: 1.3412x; 1.0019x over previous
#include <cuda_runtime.h>
#include <cuda_bf16.h>
#include <math.h>

#define B 8
#define DIM 8192
#define HEAD_DIM 128
#define N_KV 8
#define N_REP 8
#define NH 64
#define KV 4096
#define E 8
#define FD 2048
#define FE 1024
#define QKV_N 10240
#define SPLITS 32
#define JSPL (KV / SPLITS)   /* 128 */
#define JWARP (JSPL / 8)     /* 16  */

// ---------------- scratch ----------------
__device__ float g_an[B * DIM];
__device__ float g_qkv[B * QKV_N];
__device__ float g_q[B * NH * HEAD_DIM];
__device__ float g_knew[B * N_KV * HEAD_DIM];
__device__ float g_vnew[B * N_KV * HEAD_DIM];
__device__ float g_attn[B * DIM];
__device__ float g_h[B * DIM];
__device__ float g_fin[B * DIM];
__device__ float g_t1[B * FD];
__device__ float g_t3[B * FD];
__device__ float g_g[B * FD];
__device__ float g_glog[B * E];
__device__ float g_wexp[B * E];
__device__ float g_h1[B * E * FE];
__device__ float g_h3[B * E * FE];
__device__ float g_ge[B * E * FE];
__device__ float g_part_o[(size_t)B * N_KV * SPLITS * N_REP * HEAD_DIM];
__device__ float g_part_m[B * N_KV * SPLITS * N_REP];
__device__ float g_part_l[B * N_KV * SPLITS * N_REP];

// ---------------- rmsnorm ----------------
__global__ void rmsnorm_kernel(const float* __restrict__ x, const float* __restrict__ w,
                               float* __restrict__ out) {
    int b = blockIdx.x;
    const float* xb = x + (size_t)b * DIM;
    float* ob = out + (size_t)b * DIM;
    float ss = 0.f;
    for (int i = threadIdx.x; i < DIM; i += blockDim.x) {
        float v = xb[i];
        ss += v * v;
    }
    __shared__ float red[32];
    for (int off = 16; off > 0; off >>= 1) ss += __shfl_xor_sync(0xffffffffu, ss, off);
    int lane = threadIdx.x & 31, warp = threadIdx.x >> 5;
    if (lane == 0) red[warp] = ss;
    __syncthreads();
    if (warp == 0) {
        float v = (lane < (int)(blockDim.x >> 5)) ? red[lane] : 0.f;
        for (int off = 16; off > 0; off >>= 1) v += __shfl_xor_sync(0xffffffffu, v, off);
        if (lane == 0) red[0] = v;
    }
    __syncthreads();
    float scale = rsqrtf(red[0] / (float)DIM + 1e-5f);
    for (int i = threadIdx.x; i < DIM; i += blockDim.x)
        ob[i] = xb[i] * scale * w[i];
}

// ---------------- column-major GEMV (x[B,K] @ W[K,N]), k-split + atomics ----------------
__global__ void __launch_bounds__(128, 4)
gemv_cm4_kernel(const float* __restrict__ x, const float* __restrict__ W,
                float* __restrict__ out, int K, int N, int kchunk) {
    int n4 = blockIdx.x * blockDim.x + threadIdx.x;
    int N4 = N >> 2;
    int k0 = blockIdx.y * kchunk;
    __shared__ float xs[B][128];
    float acc[4][B];
#pragma unroll
    for (int r = 0; r < 4; ++r)
#pragma unroll
        for (int b = 0; b < B; ++b) acc[r][b] = 0.f;
    const float4* W4 = (const float4*)W;
    for (int kb = k0; kb < k0 + kchunk; kb += 128) {
        __syncthreads();
        for (int i = threadIdx.x; i < B * 128; i += blockDim.x)
            xs[i >> 7][i & 127] = x[(size_t)(i >> 7) * K + kb + (i & 127)];
        __syncthreads();
#pragma unroll 8
        for (int kk = 0; kk < 128; ++kk) {
            float4 w = __ldcs(W4 + (size_t)(kb + kk) * N4 + n4);
#pragma unroll
            for (int b = 0; b < B; ++b) {
                float xv = xs[b][kk];
                acc[0][b] += w.x * xv;
                acc[1][b] += w.y * xv;
                acc[2][b] += w.z * xv;
                acc[3][b] += w.w * xv;
            }
        }
    }
    int n = n4 * 4;
#pragma unroll
    for (int b = 0; b < B; ++b)
#pragma unroll
        for (int r = 0; r < 4; ++r)
            atomicAdd(&out[(size_t)b * N + n + r], acc[r][b]);
}

// ---------------- proven rm4 GEMV body (weights streamed via __ldcs) ----------------
__device__ __forceinline__ void rm4_body(const float* __restrict__ x,
                                         const float* __restrict__ W,
                                         float* __restrict__ out, int N, int K,
                                         const float* __restrict__ addsrc,
                                         int n0, int lane) {
    int K4 = K >> 2;
    const float4* x4 = (const float4*)x;
    const float4* w0 = (const float4*)(W + (size_t)(n0 + 0) * K);
    const float4* w1 = (const float4*)(W + (size_t)(n0 + 1) * K);
    const float4* w2 = (const float4*)(W + (size_t)(n0 + 2) * K);
    const float4* w3 = (const float4*)(W + (size_t)(n0 + 3) * K);
    float acc[4][B];
#pragma unroll
    for (int r = 0; r < 4; ++r)
#pragma unroll
        for (int b = 0; b < B; ++b) acc[r][b] = 0.f;
#pragma unroll 2
    for (int i = lane; i < K4; i += 32) {
        float4 xv[B];
#pragma unroll
        for (int b = 0; b < B; ++b) xv[b] = x4[(size_t)b * K4 + i];
        float4 w;
        w = __ldcs(w0 + i);
#pragma unroll
        for (int b = 0; b < B; ++b)
            acc[0][b] += w.x * xv[b].x + w.y * xv[b].y + w.z * xv[b].z + w.w * xv[b].w;
        w = __ldcs(w1 + i);
#pragma unroll
        for (int b = 0; b < B; ++b)
            acc[1][b] += w.x * xv[b].x + w.y * xv[b].y + w.z * xv[b].z + w.w * xv[b].w;
        w = __ldcs(w2 + i);
#pragma unroll
        for (int b = 0; b < B; ++b)
            acc[2][b] += w.x * xv[b].x + w.y * xv[b].y + w.z * xv[b].z + w.w * xv[b].w;
        w = __ldcs(w3 + i);
#pragma unroll
        for (int b = 0; b < B; ++b)
            acc[3][b] += w.x * xv[b].x + w.y * xv[b].y + w.z * xv[b].z + w.w * xv[b].w;
    }
#pragma unroll
    for (int r = 0; r < 4; ++r)
#pragma unroll
        for (int b = 0; b < B; ++b)
#pragma unroll
            for (int off = 16; off > 0; off >>= 1)
                acc[r][b] += __shfl_xor_sync(0xffffffffu, acc[r][b], off);
    if (lane == 0) {
#pragma unroll
        for (int r = 0; r < 4; ++r) {
            int n = n0 + r;
            if (n < N) {
#pragma unroll
                for (int b = 0; b < B; ++b) {
                    float v = acc[r][b];
                    if (addsrc) v += addsrc[(size_t)b * N + n];
                    out[(size_t)b * N + n] = v;
                }
            }
        }
    }
}

// direct-store GEMV — 128-thread blocks
__global__ void __launch_bounds__(128, 4)
gemv_rm4_kernel(const float* __restrict__ x, const float* __restrict__ W,
                float* __restrict__ out, int N, int K,
                const float* __restrict__ addsrc) {
    int warp = threadIdx.x >> 5, lane = threadIdx.x & 31;
    int n0 = (blockIdx.x * 4 + warp) * 4;
    if (n0 >= N) return;
    rm4_body(x, W, out, N, K, addsrc, n0, lane);
}

// dual (Wa,Wb via blockIdx.z) + k-split (gridDim.y) atomic; outputs pre-zeroed
__global__ void __launch_bounds__(128, 4)
gemv_rm4_dual_atomic_kernel(const float* __restrict__ x,
                            const float* __restrict__ Wa, const float* __restrict__ Wb,
                            float* __restrict__ outa, float* __restrict__ outb,
                            int N, int K) {
    const float* W = (blockIdx.z == 0) ? Wa : Wb;
    float* out = (blockIdx.z == 0) ? outa : outb;
    int warp = threadIdx.x >> 5, lane = threadIdx.x & 31;
    int n0 = (blockIdx.x * 4 + warp) * 4;
    if (n0 >= N) return;
    int K4 = K >> 2;
    int chunk = K4 / gridDim.y;
    int i0 = blockIdx.y * chunk;
    const float4* x4 = (const float4*)x;
    const float4* w0 = (const float4*)(W + (size_t)(n0 + 0) * K);
    const float4* w1 = (const float4*)(W + (size_t)(n0 + 1) * K);
    const float4* w2 = (const float4*)(W + (size_t)(n0 + 2) * K);
    const float4* w3 = (const float4*)(W + (size_t)(n0 + 3) * K);
    float acc[4][B];
#pragma unroll
    for (int r = 0; r < 4; ++r)
#pragma unroll
        for (int b = 0; b < B; ++b) acc[r][b] = 0.f;
#pragma unroll 2
    for (int i = i0 + lane; i < i0 + chunk; i += 32) {
        float4 xv[B];
#pragma unroll
        for (int b = 0; b < B; ++b) xv[b] = x4[(size_t)b * K4 + i];
        float4 w;
        w = __ldcs(w0 + i);
#pragma unroll
        for (int b = 0; b < B; ++b)
            acc[0][b] += w.x * xv[b].x + w.y * xv[b].y + w.z * xv[b].z + w.w * xv[b].w;
        w = __ldcs(w1 + i);
#pragma unroll
        for (int b = 0; b < B; ++b)
            acc[1][b] += w.x * xv[b].x + w.y * xv[b].y + w.z * xv[b].z + w.w * xv[b].w;
        w = __ldcs(w2 + i);
#pragma unroll
        for (int b = 0; b < B; ++b)
            acc[2][b] += w.x * xv[b].x + w.y * xv[b].y + w.z * xv[b].z + w.w * xv[b].w;
        w = __ldcs(w3 + i);
#pragma unroll
        for (int b = 0; b < B; ++b)
            acc[3][b] += w.x * xv[b].x + w.y * xv[b].y + w.z * xv[b].z + w.w * xv[b].w;
    }
#pragma unroll
    for (int r = 0; r < 4; ++r)
#pragma unroll
        for (int b = 0; b < B; ++b)
#pragma unroll
            for (int off = 16; off > 0; off >>= 1)
                acc[r][b] += __shfl_xor_sync(0xffffffffu, acc[r][b], off);
    if (lane == 0) {
#pragma unroll
        for (int r = 0; r < 4; ++r)
#pragma unroll
            for (int b = 0; b < B; ++b)
                atomicAdd(&out[(size_t)b * N + n0 + r], acc[r][b]);
    }
}

// MoE up: dual (w1,w3), expert skip, direct store — 128-thread blocks
__global__ void __launch_bounds__(128, 4)
moe_up_dual_kernel(const float* __restrict__ x,
                   const float* __restrict__ W1, const float* __restrict__ W3,
                   float* __restrict__ o1, float* __restrict__ o3,
                   const float* __restrict__ wexp) {
    int warp = threadIdx.x >> 5, lane = threadIdx.x & 31;
    int n0 = (blockIdx.x * 4 + warp) * 4;
    int e = n0 >> 10;   // FE = 1024; block's 16 rows stay within one expert
    __shared__ float we[B];
    if (threadIdx.x < B) we[threadIdx.x] = wexp[threadIdx.x * E + e];
    __syncthreads();
    bool any = false;
#pragma unroll
    for (int b = 0; b < B; ++b) any |= (we[b] != 0.f);
    if (!any) return;
    const float* W = (blockIdx.z == 0) ? W1 : W3;
    float* out = (blockIdx.z == 0) ? o1 : o3;
    rm4_body(x, W, out, E * FE, DIM, nullptr, n0, lane);
}

// MoE down-proj, expert skip, weighted atomic — 128-thread blocks
__global__ void __launch_bounds__(128, 4)
moe_second4_kernel(const float* __restrict__ ge, const float* __restrict__ w2,
                   const float* __restrict__ wexp, float* __restrict__ out) {
    int e = blockIdx.y;
    __shared__ float we[B];
    if (threadIdx.x < B) we[threadIdx.x] = wexp[threadIdx.x * E + e];
    __syncthreads();
    bool any = false;
#pragma unroll
    for (int b = 0; b < B; ++b) any |= (we[b] != 0.f);
    if (!any) return;

    int warp = threadIdx.x >> 5, lane = threadIdx.x & 31;
    int n0 = (blockIdx.x * 4 + warp) * 4;
    const float4* x4 = (const float4*)ge;
    int K4 = FE >> 2;
    const float4* w0 = (const float4*)(w2 + ((size_t)e * DIM + n0 + 0) * FE);
    const float4* w1 = (const float4*)(w2 + ((size_t)e * DIM + n0 + 1) * FE);
    const float4* w2p = (const float4*)(w2 + ((size_t)e * DIM + n0 + 2) * FE);
    const float4* w3 = (const float4*)(w2 + ((size_t)e * DIM + n0 + 3) * FE);
    float acc[4][B];
#pragma unroll
    for (int r = 0; r < 4; ++r)
#pragma unroll
        for (int b = 0; b < B; ++b) acc[r][b] = 0.f;
#pragma unroll 2
    for (int i = lane; i < K4; i += 32) {
        float4 xv[B];
#pragma unroll
        for (int b = 0; b < B; ++b) xv[b] = x4[((size_t)b * E + e) * K4 + i];
        float4 w;
        w = __ldcs(w0 + i);
#pragma unroll
        for (int b = 0; b < B; ++b)
            acc[0][b] += w.x * xv[b].x + w.y * xv[b].y + w.z * xv[b].z + w.w * xv[b].w;
        w = __ldcs(w1 + i);
#pragma unroll
        for (int b = 0; b < B; ++b)
            acc[1][b] += w.x * xv[b].x + w.y * xv[b].y + w.z * xv[b].z + w.w * xv[b].w;
        w = __ldcs(w2p + i);
#pragma unroll
        for (int b = 0; b < B; ++b)
            acc[2][b] += w.x * xv[b].x + w.y * xv[b].y + w.z * xv[b].z + w.w * xv[b].w;
        w = __ldcs(w3 + i);
#pragma unroll
        for (int b = 0; b < B; ++b)
            acc[3][b] += w.x * xv[b].x + w.y * xv[b].y + w.z * xv[b].z + w.w * xv[b].w;
    }
#pragma unroll
    for (int r = 0; r < 4; ++r)
#pragma unroll
        for (int b = 0; b < B; ++b)
#pragma unroll
            for (int off = 16; off > 0; off >>= 1)
                acc[r][b] += __shfl_xor_sync(0xffffffffu, acc[r][b], off);
    if (lane == 0) {
#pragma unroll
        for (int r = 0; r < 4; ++r) {
            int n = n0 + r;
#pragma unroll
            for (int b = 0; b < B; ++b)
                if (we[b] != 0.f) atomicAdd(&out[(size_t)b * DIM + n], we[b] * acc[r][b]);
        }
    }
}

// ---------------- rope + split ----------------
__global__ void rope_split_kernel(const float* __restrict__ qkv,
                                  const float* __restrict__ fc, const float* __restrict__ fs,
                                  float* __restrict__ q, float* __restrict__ knew,
                                  float* __restrict__ vnew) {
    int b = blockIdx.x;
    const float* qb = qkv + (size_t)b * QKV_N;
    for (int i = threadIdx.x; i < NH * 64; i += blockDim.x) {
        int h = i >> 6, pi = i & 63;
        int g = h >> 3, r = h & 7;
        const float* base = qb + g * 1280 + r * 128;
        float re = base[2 * pi], im = base[2 * pi + 1];
        float c = fc[pi], s = fs[pi];
        float* qo = q + ((size_t)b * NH + h) * HEAD_DIM;
        qo[2 * pi] = re * c - im * s;
        qo[2 * pi + 1] = re * s + im * c;
    }
    for (int i = threadIdx.x; i < N_KV * 64; i += blockDim.x) {
        int g = i >> 6, pi = i & 63;
        const float* base = qb + g * 1280 + 1024;
        float re = base[2 * pi], im = base[2 * pi + 1];
        float c = fc[pi], s = fs[pi];
        float* ko = knew + ((size_t)b * N_KV + g) * HEAD_DIM;
        ko[2 * pi] = re * c - im * s;
        ko[2 * pi + 1] = re * s + im * c;
    }
    for (int i = threadIdx.x; i < N_KV * HEAD_DIM; i += blockDim.x) {
        int g = i >> 7, d = i & 127;
        vnew[((size_t)b * N_KV + g) * HEAD_DIM + d] = qb[g * 1280 + 1152 + d];
    }
}

// ---------------- fused flash decode (R7 structure; SPLITS=32, KV streamed) ----------------
__global__ void __launch_bounds__(256, 4)
flash_decode_kernel(const float* __restrict__ q, const float* __restrict__ cache_k,
                    const float* __restrict__ cache_v,
                    const float* __restrict__ knew, const float* __restrict__ vnew,
                    const float* __restrict__ mask, const int* __restrict__ sp_ptr,
                    float* __restrict__ part_o, float* __restrict__ part_m,
                    float* __restrict__ part_l) {
    int split = blockIdx.x, g = blockIdx.y, b = blockIdx.z;
    int sp = *sp_ptr;
    int warp = threadIdx.x >> 5, lane = threadIdx.x & 31;
    int j0 = split * JSPL;

    __shared__ __align__(16) float s[8][JSPL + 4];   // scores (4.2 KB)
    __shared__ __align__(16) float4 sb[512];         // PV reduce buffer (8 KB)
    __shared__ float wmax[8][8];

    float4 q4[8];
    const float* qb = q + ((size_t)b * NH + g * 8) * HEAD_DIM;
#pragma unroll
    for (int r = 0; r < 8; ++r)
        q4[r] = ((const float4*)(qb + r * HEAD_DIM))[lane];

    const float scale = 0.08838834764831845f;
    float mloc = -1e30f;

    for (int jj = 0; jj < JWARP; ++jj) {
        int jl = warp * JWARP + jj;
        int j = j0 + jl;
        const float4* krow = (const float4*)((j == sp)
            ? (knew + ((size_t)b * N_KV + g) * HEAD_DIM)
            : (cache_k + (((size_t)b * KV + j) * N_KV + g) * HEAD_DIM));
        float4 k4 = __ldcs(krow + lane);
        float p[8];
#pragma unroll
        for (int r = 0; r < 8; ++r)
            p[r] = k4.x * q4[r].x + k4.y * q4[r].y + k4.z * q4[r].z + k4.w * q4[r].w;
#pragma unroll
        for (int k = 0; k < 4; ++k) {
            float a = p[2 * k], bb = p[2 * k + 1];
            float t = (lane & 1) ? a : bb;
            t = __shfl_xor_sync(0xffffffffu, t, 1);
            p[k] = ((lane & 1) ? bb : a) + t;
        }
#pragma unroll
        for (int k = 0; k < 2; ++k) {
            float a = p[2 * k], bb = p[2 * k + 1];
            float t = (lane & 2) ? a : bb;
            t = __shfl_xor_sync(0xffffffffu, t, 2);
            p[k] = ((lane & 2) ? bb : a) + t;
        }
        {
            float a = p[0], bb = p[1];
            float t = (lane & 4) ? a : bb;
            t = __shfl_xor_sync(0xffffffffu, t, 4);
            p[0] = ((lane & 4) ? bb : a) + t;
        }
        float v = p[0];
        v += __shfl_xor_sync(0xffffffffu, v, 8);
        v += __shfl_xor_sync(0xffffffffu, v, 16);
        if (lane < 8) {
            float sc = v * scale + mask[j];
            s[lane][jl] = sc;
            mloc = fmaxf(mloc, sc);
        }
    }
    if (lane < 8) wmax[warp][lane] = mloc;
    __syncthreads();

    {
        int r = warp;
        float m = wmax[0][r];
#pragma unroll
        for (int w = 1; w < 8; ++w) m = fmaxf(m, wmax[w][r]);
        float ls = 0.f;
        for (int jl = lane; jl < JSPL; jl += 32) {
            float pv = __expf(s[r][jl] - m);
            s[r][jl] = pv;
            ls += pv;
        }
#pragma unroll
        for (int off = 16; off > 0; off >>= 1) ls += __shfl_xor_sync(0xffffffffu, ls, off);
        if (lane == 0) {
            int idx = ((b * N_KV + g) * SPLITS + split) * N_REP + r;
            part_m[idx] = m;
            part_l[idx] = ls;
        }
    }
    __syncthreads();

    float4 acc[8];
#pragma unroll
    for (int r = 0; r < 8; ++r) acc[r] = make_float4(0.f, 0.f, 0.f, 0.f);
    for (int jj = 0; jj < JWARP; ++jj) {
        int jl = warp * JWARP + jj;
        int j = j0 + jl;
        const float4* vrow = (const float4*)((j == sp)
            ? (vnew + ((size_t)b * N_KV + g) * HEAD_DIM)
            : (cache_v + (((size_t)b * KV + j) * N_KV + g) * HEAD_DIM));
        float4 v4 = __ldcs(vrow + lane);
#pragma unroll
        for (int r = 0; r < 8; ++r) {
            float pr = s[r][jl];
            acc[r].x += pr * v4.x;
            acc[r].y += pr * v4.y;
            acc[r].z += pr * v4.z;
            acc[r].w += pr * v4.w;
        }
    }

    float* po = part_o + (((size_t)(b * N_KV + g) * SPLITS + split) * N_REP) * HEAD_DIM;
#pragma unroll
    for (int rg = 0; rg < 4; ++rg) {
        __syncthreads();
        sb[(warp * 2 + 0) * 32 + lane] = acc[rg * 2 + 0];
        sb[(warp * 2 + 1) * 32 + lane] = acc[rg * 2 + 1];
        __syncthreads();
        int rrl = threadIdx.x >> 7;
        int d = threadIdx.x & 127;
        float v = 0.f;
        const float* sf = (const float*)sb;
#pragma unroll
        for (int w = 0; w < 8; ++w)
            v += sf[(w * 2 + rrl) * 128 + d];
        po[(rg * 2 + rrl) * HEAD_DIM + d] = v;
    }
}

// ---------------- combine splits (part_o streamed) ----------------
__global__ void combine_kernel(const float* __restrict__ part_o, const float* __restrict__ part_m,
                               const float* __restrict__ part_l, float* __restrict__ attn) {
    int head = blockIdx.x & 63, b = blockIdx.x >> 6;
    int g = head >> 3, r = head & 7;
    int d = threadIdx.x;
    float M = -1e30f;
#pragma unroll
    for (int sp = 0; sp < SPLITS; ++sp)
        M = fmaxf(M, part_m[((b * N_KV + g) * SPLITS + sp) * N_REP + r]);
    float L = 0.f, acc = 0.f;
#pragma unroll
    for (int sp = 0; sp < SPLITS; ++sp) {
        int idx = ((b * N_KV + g) * SPLITS + sp) * N_REP + r;
        float w = __expf(part_m[idx] - M);
        L += w * part_l[idx];
        acc += w * __ldcs(part_o + (((size_t)(b * N_KV + g) * SPLITS + sp) * N_REP + r) * HEAD_DIM + d);
    }
    attn[((size_t)b * NH + head) * HEAD_DIM + d] = acc / L;
}

// ---------------- gelu(t1)*t3 ----------------
__global__ void gelumul_kernel(const float* __restrict__ t1, const float* __restrict__ t3,
                               float* __restrict__ g, int n) {
    int i = blockIdx.x * blockDim.x + threadIdx.x;
    if (i < n) {
        float x = __ldcs(t1 + i);
        g[i] = 0.5f * x * (1.f + erff(x * 0.7071067811865476f)) * __ldcs(t3 + i);
    }
}

// ---------------- gate softmax + top-2 ----------------
__global__ void gate_topk_kernel(const float* __restrict__ logits, float* __restrict__ wexp) {
    int b = threadIdx.x;
    if (b >= B) return;
    float l[E];
    float m = -1e30f;
#pragma unroll
    for (int e = 0; e < E; ++e) { l[e] = logits[b * E + e]; m = fmaxf(m, l[e]); }
    float sum = 0.f;
#pragma unroll
    for (int e = 0; e < E; ++e) { l[e] = expf(l[e] - m); sum += l[e]; }
#pragma unroll
    for (int e = 0; e < E; ++e) l[e] /= sum;
    int i1 = 0;
#pragma unroll
    for (int e = 1; e < E; ++e) if (l[e] > l[i1]) i1 = e;
    int i2 = (i1 == 0) ? 1 : 0;
#pragma unroll
    for (int e = 0; e < E; ++e) if (e != i1 && l[e] > l[i2]) i2 = e;
#pragma unroll
    for (int e = 0; e < E; ++e)
        wexp[b * E + e] = (e == i1) ? l[i1] : (e == i2) ? l[i2] : 0.f;
}

// ---------------- launch ----------------
extern "C" void kernel_launch(void* const* d_in, const int* in_sizes, int n_in,
                              void* d_out, int out_size) {
    const float* x        = (const float*)d_in[0];
    const float* mask     = (const float*)d_in[1];
    const float* fcos     = (const float*)d_in[2];
    const float* fsin     = (const float*)d_in[3];
    const float* cache_k  = (const float*)d_in[4];
    const float* cache_v  = (const float*)d_in[5];
    const float* wqkv     = (const float*)d_in[6];
    const float* wo       = (const float*)d_in[7];
    const float* attn_nw  = (const float*)d_in[8];
    const float* ffn_nw   = (const float*)d_in[9];
    const float* ffn_w1   = (const float*)d_in[10];
    const float* ffn_w2   = (const float*)d_in[11];
    const float* ffn_w3   = (const float*)d_in[12];
    const float* gate_w   = (const float*)d_in[13];
    const float* moe_w1   = (const float*)d_in[14];
    const float* moe_w2   = (const float*)d_in[15];
    const float* moe_w3   = (const float*)d_in[16];
    const int*   sp       = (const int*)d_in[17];
    float* out            = (float*)d_out;

    float *an, *qkv, *q, *knew, *vnew, *attn, *h, *fin, *t1, *t3, *gg;
    float *glog, *wexp, *h1, *h3, *ge, *po, *pm, *pl;
    cudaGetSymbolAddress((void**)&an, g_an);
    cudaGetSymbolAddress((void**)&qkv, g_qkv);
    cudaGetSymbolAddress((void**)&q, g_q);
    cudaGetSymbolAddress((void**)&knew, g_knew);
    cudaGetSymbolAddress((void**)&vnew, g_vnew);
    cudaGetSymbolAddress((void**)&attn, g_attn);
    cudaGetSymbolAddress((void**)&h, g_h);
    cudaGetSymbolAddress((void**)&fin, g_fin);
    cudaGetSymbolAddress((void**)&t1, g_t1);
    cudaGetSymbolAddress((void**)&t3, g_t3);
    cudaGetSymbolAddress((void**)&gg, g_g);
    cudaGetSymbolAddress((void**)&glog, g_glog);
    cudaGetSymbolAddress((void**)&wexp, g_wexp);
    cudaGetSymbolAddress((void**)&h1, g_h1);
    cudaGetSymbolAddress((void**)&h3, g_h3);
    cudaGetSymbolAddress((void**)&ge, g_ge);
    cudaGetSymbolAddress((void**)&po, g_part_o);
    cudaGetSymbolAddress((void**)&pm, g_part_m);
    cudaGetSymbolAddress((void**)&pl, g_part_l);

    cudaMemsetAsync(qkv, 0, sizeof(float) * B * QKV_N);
    cudaMemsetAsync(t1, 0, sizeof(float) * B * FD);
    cudaMemsetAsync(t3, 0, sizeof(float) * B * FD);

    // attention
    rmsnorm_kernel<<<B, 1024>>>(x, attn_nw, an);
    gemv_cm4_kernel<<<dim3((QKV_N / 4) / 128, 16), 128>>>(an, wqkv, qkv, DIM, QKV_N, DIM / 16);
    rope_split_kernel<<<B, 512>>>(qkv, fcos, fsin, q, knew, vnew);
    flash_decode_kernel<<<dim3(SPLITS, N_KV, B), 256>>>(q, cache_k, cache_v, knew, vnew,
                                                        mask, sp, po, pm, pl);
    combine_kernel<<<B * NH, HEAD_DIM>>>(po, pm, pl, attn);
    gemv_rm4_kernel<<<DIM / 16, 128>>>(attn, wo, h, DIM, DIM, x);   // h = x + attn@wo.T

    // ffn + moe
    rmsnorm_kernel<<<B, 1024>>>(h, ffn_nw, fin);
    gemv_rm4_kernel<<<1, 128>>>(fin, gate_w, glog, E, DIM, nullptr);
    gate_topk_kernel<<<1, 32>>>(glog, wexp);
    gemv_rm4_dual_atomic_kernel<<<dim3(FD / 16, 2, 2), 128>>>(fin, ffn_w1, ffn_w3, t1, t3, FD, DIM);
    gelumul_kernel<<<(B * FD) / 256, 256>>>(t1, t3, gg, B * FD);
    gemv_rm4_kernel<<<DIM / 16, 128>>>(gg, ffn_w2, out, DIM, FD, h);  // out = h + ff
    moe_up_dual_kernel<<<dim3((E * FE) / 16, 1, 2), 128>>>(fin, moe_w1, moe_w3, h1, h3, wexp);
    gelumul_kernel<<<(B * E * FE) / 256, 256>>>(h1, h3, ge, B * E * FE);
    moe_second4_kernel<<<dim3(DIM / 16, E), 128>>>(ge, moe_w2, wexp, out);  // out += moe
}